// round 2
// baseline (speedup 1.0000x reference)
#include <cuda_runtime.h>
#include <math.h>
#include <stdint.h>

#define EMB_EDGE 512
#define EMB_RBF  16
#define EMB_CBF  16
#define EMB_TRI  64
#define EMB_BIL  64
#define E_MAX    65536
#define T_MAX    262144

// scratch (device globals: allocation-free rule)
__device__ float g_h1[(size_t)E_MAX * EMB_EDGE];          // 128 MB
__device__ float g_mkt[(size_t)E_MAX * EMB_TRI];          // 16 MB
__device__ float g_S[(size_t)E_MAX * EMB_CBF * EMB_TRI];  // 256 MB
__device__ float g_x[(size_t)E_MAX * EMB_BIL];            // 16 MB
__device__ int   g_segptr[E_MAX + 1];

__device__ __forceinline__ float silu_f(float v) {
    return v / (1.0f + __expf(-v));
}

// ---------------------------------------------------------------------------
// Kernel 1: h1 = silu(m_st @ W_mkt) * (rbf @ W_rbf) * s_rbf
// M x 512 x 512, BM=128 BN=128 BK=16, 256 thr, 8x8 microtile
// ---------------------------------------------------------------------------
__global__ void k_gemm1(const float* __restrict__ A, const float* __restrict__ B,
                        const float* __restrict__ rbf, const float* __restrict__ Wr,
                        const float* __restrict__ s_rbf, float* __restrict__ C, int M)
{
    __shared__ float As[16][128];
    __shared__ float Bs[16][128];
    const int tid = threadIdx.x;
    const int tx = tid & 15, ty = tid >> 4;
    const int row0 = blockIdx.y * 128;
    const int col0 = blockIdx.x * 128;

    float acc[8][8] = {};

    for (int k0 = 0; k0 < 512; k0 += 16) {
        #pragma unroll
        for (int p = 0; p < 2; p++) {
            int l = p * 256 + tid;
            int r = l >> 2, q = (l & 3) * 4;
            float4 v = *(const float4*)(A + (size_t)(row0 + r) * 512 + k0 + q);
            As[q + 0][r] = v.x; As[q + 1][r] = v.y;
            As[q + 2][r] = v.z; As[q + 3][r] = v.w;
        }
        #pragma unroll
        for (int p = 0; p < 2; p++) {
            int l = p * 256 + tid;
            int r = l >> 5, c = (l & 31) * 4;
            *(float4*)&Bs[r][c] = *(const float4*)(B + (size_t)(k0 + r) * 512 + col0 + c);
        }
        __syncthreads();
        #pragma unroll
        for (int k = 0; k < 16; k++) {
            float a[8], b[8];
            #pragma unroll
            for (int i = 0; i < 8; i++) a[i] = As[k][ty * 8 + i];
            #pragma unroll
            for (int j = 0; j < 8; j++) b[j] = Bs[k][tx * 8 + j];
            #pragma unroll
            for (int i = 0; i < 8; i++)
                #pragma unroll
                for (int j = 0; j < 8; j++) acc[i][j] = fmaf(a[i], b[j], acc[i][j]);
        }
        __syncthreads();
    }

    // epilogue: rbf modulation.  Reuse As for Wr tile [16][128], Bs for rbf^T [16][128]
    #pragma unroll
    for (int p = 0; p < 2; p++) {
        int l = p * 256 + tid;
        int r = l >> 5, c = (l & 31) * 4;
        *(float4*)&As[r][c] = *(const float4*)(Wr + (size_t)r * 512 + col0 + c);
    }
    #pragma unroll
    for (int p = 0; p < 2; p++) {
        int l = p * 256 + tid;
        int rr = l >> 2, q = (l & 3) * 4;
        float4 v = *(const float4*)(rbf + (size_t)(row0 + rr) * 16 + q);
        Bs[q + 0][rr] = v.x; Bs[q + 1][rr] = v.y;
        Bs[q + 2][rr] = v.z; Bs[q + 3][rr] = v.w;
    }
    __syncthreads();

    const float s = *s_rbf;
    #pragma unroll
    for (int i = 0; i < 8; i++) {
        float mod[8] = {};
        #pragma unroll
        for (int q = 0; q < 16; q++) {
            float rv = Bs[q][ty * 8 + i];
            #pragma unroll
            for (int j = 0; j < 8; j++) mod[j] = fmaf(rv, As[q][tx * 8 + j], mod[j]);
        }
        float* crow = C + (size_t)(row0 + ty * 8 + i) * 512 + col0 + tx * 8;
        float4 o0, o1;
        o0.x = silu_f(acc[i][0]) * mod[0] * s;
        o0.y = silu_f(acc[i][1]) * mod[1] * s;
        o0.z = silu_f(acc[i][2]) * mod[2] * s;
        o0.w = silu_f(acc[i][3]) * mod[3] * s;
        o1.x = silu_f(acc[i][4]) * mod[4] * s;
        o1.y = silu_f(acc[i][5]) * mod[5] * s;
        o1.z = silu_f(acc[i][6]) * mod[6] * s;
        o1.w = silu_f(acc[i][7]) * mod[7] * s;
        *(float4*)(crow)     = o0;
        *(float4*)(crow + 4) = o1;
    }
}

// ---------------------------------------------------------------------------
// Generic M x KDIM x 64 GEMM. BM=128 BN=64 BK=16, 256 thr, 8x4 microtile
// used for: m_kt = silu(h1 @ W_down)   and   x = (S @ W_bil) * s_cbf
// ---------------------------------------------------------------------------
template<int KDIM, bool DO_SILU, bool DO_SCALE>
__global__ void k_gemm_n64(const float* __restrict__ A, const float* __restrict__ B,
                           const float* __restrict__ scale, float* __restrict__ C, int M)
{
    __shared__ float As[16][128];
    __shared__ float Bs[16][64];
    const int tid = threadIdx.x;
    const int row0 = blockIdx.y * 128;
    const int tx = tid & 15, ty = tid >> 4;

    float acc[8][4] = {};

    for (int k0 = 0; k0 < KDIM; k0 += 16) {
        #pragma unroll
        for (int p = 0; p < 2; p++) {
            int l = p * 256 + tid;
            int r = l >> 2, q = (l & 3) * 4;
            float4 v = *(const float4*)(A + (size_t)(row0 + r) * KDIM + k0 + q);
            As[q + 0][r] = v.x; As[q + 1][r] = v.y;
            As[q + 2][r] = v.z; As[q + 3][r] = v.w;
        }
        {
            int r = tid >> 4, q = (tid & 15) * 4;
            *(float4*)&Bs[r][q] = *(const float4*)(B + (size_t)(k0 + r) * 64 + q);
        }
        __syncthreads();
        #pragma unroll
        for (int k = 0; k < 16; k++) {
            float a[8], b[4];
            #pragma unroll
            for (int i = 0; i < 8; i++) a[i] = As[k][ty * 8 + i];
            #pragma unroll
            for (int j = 0; j < 4; j++) b[j] = Bs[k][tx * 4 + j];
            #pragma unroll
            for (int i = 0; i < 8; i++)
                #pragma unroll
                for (int j = 0; j < 4; j++) acc[i][j] = fmaf(a[i], b[j], acc[i][j]);
        }
        __syncthreads();
    }

    float sc = 1.0f;
    if (DO_SCALE) sc = *scale;
    #pragma unroll
    for (int i = 0; i < 8; i++) {
        float v0 = acc[i][0], v1 = acc[i][1], v2 = acc[i][2], v3 = acc[i][3];
        if (DO_SILU) { v0 = silu_f(v0); v1 = silu_f(v1); v2 = silu_f(v2); v3 = silu_f(v3); }
        float4 o = make_float4(v0 * sc, v1 * sc, v2 * sc, v3 * sc);
        *(float4*)(C + (size_t)(row0 + ty * 8 + i) * 64 + tx * 4) = o;
    }
}

// ---------------------------------------------------------------------------
// segment pointers: seg_ptr[e] = lower_bound(id3_st, e); seg_ptr[M] = T
// (id3_st is sorted, so each edge's triplets are contiguous)
// ---------------------------------------------------------------------------
__global__ void k_segptr(const int* __restrict__ st, int Tn, int M)
{
    int e = blockIdx.x * blockDim.x + threadIdx.x;
    if (e > M) return;
    if (e == M) { g_segptr[M] = Tn; return; }
    int lo = 0, hi = Tn;
    while (lo < hi) {
        int mid = (lo + hi) >> 1;
        if (st[mid] < e) lo = mid + 1; else hi = mid;
    }
    g_segptr[e] = lo;
}

// ---------------------------------------------------------------------------
// S[e,i,j] = sum_{t in seg(e)} cbf[t,i] * m_kt[id3_kt[t], j]
// one block per edge, 256 threads, 4 accumulators each (16*64 = 1024)
// ---------------------------------------------------------------------------
__global__ void k_bilS(const float* __restrict__ cbf, const int* __restrict__ id3_kt)
{
    const int e = blockIdx.x;
    const int tid = threadIdx.x;
    const int t0 = g_segptr[e], t1 = g_segptr[e + 1];
    __shared__ float sc[16];
    __shared__ float smv[64];
    float a0 = 0.f, a1 = 0.f, a2 = 0.f, a3 = 0.f;
    const int i = tid >> 4;          // cbf index  (tid*4 / 64)
    const int j = (tid * 4) & 63;    // tri index

    for (int t = t0; t < t1; t++) {
        if (tid < 16)       sc[tid]       = cbf[(size_t)t * 16 + tid];
        else if (tid < 80)  smv[tid - 16] = g_mkt[(size_t)id3_kt[t] * 64 + (tid - 16)];
        __syncthreads();
        float cv = sc[i];
        a0 = fmaf(cv, smv[j + 0], a0);
        a1 = fmaf(cv, smv[j + 1], a1);
        a2 = fmaf(cv, smv[j + 2], a2);
        a3 = fmaf(cv, smv[j + 3], a3);
        __syncthreads();
    }
    *(float4*)(g_S + (size_t)e * 1024 + tid * 4) = make_float4(a0, a1, a2, a3);
}

// ---------------------------------------------------------------------------
// out[e,c] = (silu(x[e]@W_st[:,c]) + silu(x[idx_swap[e]]@W_ts[:,c])) / sqrt(2)
// BM=64 edges, BN=64 cols, K=64 fully in smem. 256 thr, 4x4 microtile.
// ---------------------------------------------------------------------------
__global__ void k_out(const float* __restrict__ Wst, const float* __restrict__ Wts,
                      const int* __restrict__ idx_swap, float* __restrict__ out, int M)
{
    extern __shared__ float sm[];
    float* Xst = sm;                 // [64][65] (k-major, padded)
    float* Xgt = Xst + 64 * 65;      // [64][65]
    float* Ws  = Xgt + 64 * 65;      // [64][64]
    float* Wt  = Ws + 64 * 64;       // [64][64]
    const int tid = threadIdx.x;
    const int e0 = blockIdx.y * 64;
    const int col0 = blockIdx.x * 64;

    #pragma unroll
    for (int p = 0; p < 4; p++) {
        int l = p * 256 + tid;             // 0..1023
        int r = l >> 4, q = (l & 15) * 4;
        float4 v = *(const float4*)(g_x + (size_t)(e0 + r) * 64 + q);
        Xst[(q + 0) * 65 + r] = v.x; Xst[(q + 1) * 65 + r] = v.y;
        Xst[(q + 2) * 65 + r] = v.z; Xst[(q + 3) * 65 + r] = v.w;
        int ge = idx_swap[e0 + r];
        float4 g = *(const float4*)(g_x + (size_t)ge * 64 + q);
        Xgt[(q + 0) * 65 + r] = g.x; Xgt[(q + 1) * 65 + r] = g.y;
        Xgt[(q + 2) * 65 + r] = g.z; Xgt[(q + 3) * 65 + r] = g.w;
        *(float4*)&Ws[r * 64 + q] = *(const float4*)(Wst + (size_t)r * 512 + col0 + q);
        *(float4*)&Wt[r * 64 + q] = *(const float4*)(Wts + (size_t)r * 512 + col0 + q);
    }
    __syncthreads();

    const int tx = tid & 15, ty = tid >> 4;
    const int rb = ty * 4, cb = tx * 4;
    float accA[4][4] = {}, accB[4][4] = {};
    #pragma unroll
    for (int k = 0; k < 64; k++) {
        float q1[4], q2[4], b1[4], b2[4];
        #pragma unroll
        for (int i = 0; i < 4; i++) { q1[i] = Xst[k * 65 + rb + i]; q2[i] = Xgt[k * 65 + rb + i]; }
        #pragma unroll
        for (int j = 0; j < 4; j++) { b1[j] = Ws[k * 64 + cb + j]; b2[j] = Wt[k * 64 + cb + j]; }
        #pragma unroll
        for (int i = 0; i < 4; i++)
            #pragma unroll
            for (int j = 0; j < 4; j++) {
                accA[i][j] = fmaf(q1[i], b1[j], accA[i][j]);
                accB[i][j] = fmaf(q2[i], b2[j], accB[i][j]);
            }
    }

    const float inv_sqrt2 = 0.70710678118654752f;
    #pragma unroll
    for (int i = 0; i < 4; i++) {
        float4 o;
        o.x = (silu_f(accA[i][0]) + silu_f(accB[i][0])) * inv_sqrt2;
        o.y = (silu_f(accA[i][1]) + silu_f(accB[i][1])) * inv_sqrt2;
        o.z = (silu_f(accA[i][2]) + silu_f(accB[i][2])) * inv_sqrt2;
        o.w = (silu_f(accA[i][3]) + silu_f(accB[i][3])) * inv_sqrt2;
        *(float4*)(out + (size_t)(e0 + rb + i) * 512 + col0 + cb) = o;
    }
}

// ---------------------------------------------------------------------------
extern "C" void kernel_launch(void* const* d_in, const int* in_sizes, int n_in,
                              void* d_out, int out_size)
{
    const float* m_st     = (const float*)d_in[0];
    const float* rbf      = (const float*)d_in[1];
    const float* cbf      = (const float*)d_in[2];
    const int*   idx_swap = (const int*)  d_in[3];
    const int*   id3_kt   = (const int*)  d_in[4];
    const int*   id3_st   = (const int*)  d_in[5];
    /* d_in[6] = id3_ragged_idx (unused) */
    const float* W_mkt    = (const float*)d_in[7];
    const float* W_rbf    = (const float*)d_in[8];
    const float* W_down   = (const float*)d_in[9];
    const float* W_bil    = (const float*)d_in[10];
    const float* W_st     = (const float*)d_in[11];
    const float* W_ts     = (const float*)d_in[12];
    const float* s_rbf    = (const float*)d_in[13];
    const float* s_cbf    = (const float*)d_in[14];
    float* out = (float*)d_out;

    const int M  = in_sizes[0] / EMB_EDGE;   // 65536
    const int Tn = in_sizes[2] / EMB_CBF;    // 262144

    float *p_h1, *p_mkt, *p_S, *p_x;
    cudaGetSymbolAddress((void**)&p_h1,  g_h1);
    cudaGetSymbolAddress((void**)&p_mkt, g_mkt);
    cudaGetSymbolAddress((void**)&p_S,   g_S);
    cudaGetSymbolAddress((void**)&p_x,   g_x);

    // 1. h1 = silu(m_st @ W_mkt) * (rbf @ W_rbf) * s_rbf
    k_gemm1<<<dim3(4, M / 128), 256>>>(m_st, W_mkt, rbf, W_rbf, s_rbf, p_h1, M);
    // 2. m_kt = silu(h1 @ W_down)
    k_gemm_n64<512, true, false><<<dim3(1, M / 128), 256>>>(p_h1, W_down, nullptr, p_mkt, M);
    // 3. segment pointers from sorted id3_st
    k_segptr<<<(M + 256) / 256, 256>>>(id3_st, Tn, M);
    // 4. S[e,i,j] = segment-sum of cbf outer m_t
    k_bilS<<<M, 256>>>(cbf, id3_kt);
    // 5. x = (S @ W_bil) * s_cbf
    k_gemm_n64<1024, false, true><<<dim3(1, M / 128), 256>>>(p_S, W_bil, s_cbf, p_x, M);
    // 6. out = (silu(x@W_st) + silu(x[swap]@W_ts)) / sqrt(2)
    cudaFuncSetAttribute(k_out, cudaFuncAttributeMaxDynamicSharedMemorySize, 66048);
    k_out<<<dim3(8, M / 64), 256, 66048>>>(W_st, W_ts, idx_swap, out, M);
}

// round 3
// speedup vs baseline: 1.4176x; 1.4176x over previous
#include <cuda_runtime.h>
#include <math.h>
#include <stdint.h>

#define EMB_EDGE 512
#define EMB_RBF  16
#define EMB_CBF  16
#define EMB_TRI  64
#define EMB_BIL  64
#define E_MAX    65536
#define T_MAX    262144

// scratch (device globals: allocation-free rule)
__device__ float g_h1[(size_t)E_MAX * EMB_EDGE];          // 128 MB
__device__ float g_mkt[(size_t)E_MAX * EMB_TRI];          // 16 MB
__device__ float g_S[(size_t)E_MAX * EMB_CBF * EMB_TRI];  // 256 MB
__device__ float g_x[(size_t)E_MAX * EMB_BIL];            // 16 MB
__device__ int   g_segptr[E_MAX + 1];

__device__ __forceinline__ float silu_f(float v) {
    return v / (1.0f + __expf(-v));
}

__device__ __forceinline__ uint32_t f2tf32(float f) {
    uint32_t u;
    asm("cvt.rna.tf32.f32 %0, %1;" : "=r"(u) : "f"(f));
    return u;
}

__device__ __forceinline__ void mma_tf32(float& d0, float& d1, float& d2, float& d3,
                                         uint32_t a0, uint32_t a1, uint32_t a2, uint32_t a3,
                                         uint32_t b0, uint32_t b1)
{
    asm volatile(
        "mma.sync.aligned.m16n8k8.row.col.f32.tf32.tf32.f32 "
        "{%0,%1,%2,%3}, {%4,%5,%6,%7}, {%8,%9}, {%0,%1,%2,%3};\n"
        : "+f"(d0), "+f"(d1), "+f"(d2), "+f"(d3)
        : "r"(a0), "r"(a1), "r"(a2), "r"(a3), "r"(b0), "r"(b1));
}

// ---------------------------------------------------------------------------
// Kernel 1 (tensor core, tf32):
//   h1 = silu(m_st @ W_mkt) * (rbf @ W_rbf) * s_rbf
// M x 512 x 512. Block tile 128x128, BK=32, 8 warps (4m x 2n), warp tile 32x64
// ---------------------------------------------------------------------------
#define A_PAD 36    // floats per A smem row  (bank-conflict-free: 4*grp+thr4)
#define B_PAD 136   // floats per B smem row  (bank-conflict-free: 8*thr4+grp)

__global__ void k_gemm1_tc(const float* __restrict__ A, const float* __restrict__ B,
                           const float* __restrict__ rbf, const float* __restrict__ Wr,
                           const float* __restrict__ s_rbf, float* __restrict__ C, int M)
{
    __shared__ __align__(16) char smem_raw[128 * A_PAD * 4 + 32 * B_PAD * 4];
    uint32_t* As = (uint32_t*)smem_raw;            // [128][A_PAD] row-major (m, k)
    uint32_t* Bs = As + 128 * A_PAD;               // [32][B_PAD]  k-major  (k, n)

    const int tid  = threadIdx.x;
    const int warp = tid >> 5;
    const int lane = tid & 31;
    const int grp  = lane >> 2;      // 0..7
    const int thr4 = lane & 3;       // 0..3
    const int warp_m = warp & 3;     // 0..3  -> m offset warp_m*32
    const int warp_n = warp >> 2;    // 0..1  -> n offset warp_n*64
    const int row0 = blockIdx.y * 128;
    const int col0 = blockIdx.x * 128;

    float acc[2][8][4];
    #pragma unroll
    for (int mi = 0; mi < 2; mi++)
        #pragma unroll
        for (int ni = 0; ni < 8; ni++)
            #pragma unroll
            for (int q = 0; q < 4; q++) acc[mi][ni][q] = 0.f;

    const int a_row = tid >> 3;          // 0..31
    const int a_kq  = (tid & 7) * 4;     // 0..28
    const int b_r   = tid >> 5;          // 0..7
    const int b_c   = (tid & 31) * 4;    // 0..124

    for (int k0 = 0; k0 < 512; k0 += 32) {
        // load A tile 128x32 (coalesced: 8 lanes cover one row's 32 floats)
        #pragma unroll
        for (int p = 0; p < 4; p++) {
            int row = a_row + p * 32;
            float4 v = *(const float4*)(A + (size_t)(row0 + row) * 512 + k0 + a_kq);
            uint4 u = make_uint4(f2tf32(v.x), f2tf32(v.y), f2tf32(v.z), f2tf32(v.w));
            *(uint4*)(As + row * A_PAD + a_kq) = u;
        }
        // load B tile 32x128
        #pragma unroll
        for (int p = 0; p < 4; p++) {
            int r = b_r + p * 8;
            float4 v = *(const float4*)(B + (size_t)(k0 + r) * 512 + col0 + b_c);
            uint4 u = make_uint4(f2tf32(v.x), f2tf32(v.y), f2tf32(v.z), f2tf32(v.w));
            *(uint4*)(Bs + r * B_PAD + b_c) = u;
        }
        __syncthreads();

        #pragma unroll
        for (int kk = 0; kk < 4; kk++) {
            const int k8 = kk * 8;
            uint32_t a[2][4], b[8][2];
            #pragma unroll
            for (int mi = 0; mi < 2; mi++) {
                int r = warp_m * 32 + mi * 16 + grp;
                a[mi][0] = As[(r    ) * A_PAD + k8 + thr4    ];
                a[mi][1] = As[(r + 8) * A_PAD + k8 + thr4    ];
                a[mi][2] = As[(r    ) * A_PAD + k8 + thr4 + 4];
                a[mi][3] = As[(r + 8) * A_PAD + k8 + thr4 + 4];
            }
            #pragma unroll
            for (int ni = 0; ni < 8; ni++) {
                int c = warp_n * 64 + ni * 8 + grp;
                b[ni][0] = Bs[(k8 + thr4    ) * B_PAD + c];
                b[ni][1] = Bs[(k8 + thr4 + 4) * B_PAD + c];
            }
            #pragma unroll
            for (int mi = 0; mi < 2; mi++)
                #pragma unroll
                for (int ni = 0; ni < 8; ni++)
                    mma_tf32(acc[mi][ni][0], acc[mi][ni][1], acc[mi][ni][2], acc[mi][ni][3],
                             a[mi][0], a[mi][1], a[mi][2], a[mi][3],
                             b[ni][0], b[ni][1]);
        }
        __syncthreads();
    }

    // ---- epilogue: mod = rbf(128x16) @ Wr(16x128), out = silu(acc)*mod*s ----
    float* rbf_s = (float*)smem_raw;            // [128][17]
    float* Wr_s  = rbf_s + 128 * 17;            // [16][132]

    {   // rbf rows for this block: 2048 floats / 256 thr = 8 each
        int r = tid >> 1, q0 = (tid & 1) * 8;
        float4 v0 = *(const float4*)(rbf + (size_t)(row0 + r) * 16 + q0);
        float4 v1 = *(const float4*)(rbf + (size_t)(row0 + r) * 16 + q0 + 4);
        rbf_s[r * 17 + q0 + 0] = v0.x; rbf_s[r * 17 + q0 + 1] = v0.y;
        rbf_s[r * 17 + q0 + 2] = v0.z; rbf_s[r * 17 + q0 + 3] = v0.w;
        rbf_s[r * 17 + q0 + 4] = v1.x; rbf_s[r * 17 + q0 + 5] = v1.y;
        rbf_s[r * 17 + q0 + 6] = v1.z; rbf_s[r * 17 + q0 + 7] = v1.w;
        // Wr tile 16x128: 2048 floats
        int q = tid >> 4, c = (tid & 15) * 8;
        float4 w0 = *(const float4*)(Wr + (size_t)q * 512 + col0 + c);
        float4 w1 = *(const float4*)(Wr + (size_t)q * 512 + col0 + c + 4);
        *(float4*)(Wr_s + q * 132 + c)     = w0;
        *(float4*)(Wr_s + q * 132 + c + 4) = w1;
    }
    __syncthreads();

    const float s = *s_rbf;
    #pragma unroll
    for (int mi = 0; mi < 2; mi++) {
        int r_lo = warp_m * 32 + mi * 16 + grp;
        int r_hi = r_lo + 8;
        float rlo[16], rhi[16];
        #pragma unroll
        for (int q = 0; q < 16; q++) {
            rlo[q] = rbf_s[r_lo * 17 + q];
            rhi[q] = rbf_s[r_hi * 17 + q];
        }
        #pragma unroll
        for (int ni = 0; ni < 8; ni++) {
            int c_s = warp_n * 64 + ni * 8 + thr4 * 2;
            float m00 = 0.f, m01 = 0.f, m10 = 0.f, m11 = 0.f;
            #pragma unroll
            for (int q = 0; q < 16; q++) {
                float w0 = Wr_s[q * 132 + c_s];
                float w1 = Wr_s[q * 132 + c_s + 1];
                m00 = fmaf(rlo[q], w0, m00); m01 = fmaf(rlo[q], w1, m01);
                m10 = fmaf(rhi[q], w0, m10); m11 = fmaf(rhi[q], w1, m11);
            }
            float2 o_lo, o_hi;
            o_lo.x = silu_f(acc[mi][ni][0]) * m00 * s;
            o_lo.y = silu_f(acc[mi][ni][1]) * m01 * s;
            o_hi.x = silu_f(acc[mi][ni][2]) * m10 * s;
            o_hi.y = silu_f(acc[mi][ni][3]) * m11 * s;
            *(float2*)(C + (size_t)(row0 + r_lo) * 512 + col0 + c_s) = o_lo;
            *(float2*)(C + (size_t)(row0 + r_hi) * 512 + col0 + c_s) = o_hi;
        }
    }
}

// ---------------------------------------------------------------------------
// Generic M x KDIM x 64 GEMM. BM=128 BN=64 BK=16, 256 thr, 8x4 microtile
// used for: m_kt = silu(h1 @ W_down)   and   x = (S @ W_bil) * s_cbf
// ---------------------------------------------------------------------------
template<int KDIM, bool DO_SILU, bool DO_SCALE>
__global__ void k_gemm_n64(const float* __restrict__ A, const float* __restrict__ B,
                           const float* __restrict__ scale, float* __restrict__ C, int M)
{
    __shared__ float As[16][128];
    __shared__ float Bs[16][64];
    const int tid = threadIdx.x;
    const int row0 = blockIdx.y * 128;
    const int tx = tid & 15, ty = tid >> 4;

    float acc[8][4] = {};

    for (int k0 = 0; k0 < KDIM; k0 += 16) {
        #pragma unroll
        for (int p = 0; p < 2; p++) {
            int l = p * 256 + tid;
            int r = l >> 2, q = (l & 3) * 4;
            float4 v = *(const float4*)(A + (size_t)(row0 + r) * KDIM + k0 + q);
            As[q + 0][r] = v.x; As[q + 1][r] = v.y;
            As[q + 2][r] = v.z; As[q + 3][r] = v.w;
        }
        {
            int r = tid >> 4, q = (tid & 15) * 4;
            *(float4*)&Bs[r][q] = *(const float4*)(B + (size_t)(k0 + r) * 64 + q);
        }
        __syncthreads();
        #pragma unroll
        for (int k = 0; k < 16; k++) {
            float a[8], b[4];
            #pragma unroll
            for (int i = 0; i < 8; i++) a[i] = As[k][ty * 8 + i];
            #pragma unroll
            for (int j = 0; j < 4; j++) b[j] = Bs[k][tx * 4 + j];
            #pragma unroll
            for (int i = 0; i < 8; i++)
                #pragma unroll
                for (int j = 0; j < 4; j++) acc[i][j] = fmaf(a[i], b[j], acc[i][j]);
        }
        __syncthreads();
    }

    float sc = 1.0f;
    if (DO_SCALE) sc = *scale;
    #pragma unroll
    for (int i = 0; i < 8; i++) {
        float v0 = acc[i][0], v1 = acc[i][1], v2 = acc[i][2], v3 = acc[i][3];
        if (DO_SILU) { v0 = silu_f(v0); v1 = silu_f(v1); v2 = silu_f(v2); v3 = silu_f(v3); }
        float4 o = make_float4(v0 * sc, v1 * sc, v2 * sc, v3 * sc);
        *(float4*)(C + (size_t)(row0 + ty * 8 + i) * 64 + tx * 4) = o;
    }
}

// ---------------------------------------------------------------------------
// segment pointers: seg_ptr[e] = lower_bound(id3_st, e); seg_ptr[M] = T
// ---------------------------------------------------------------------------
__global__ void k_segptr(const int* __restrict__ st, int Tn, int M)
{
    int e = blockIdx.x * blockDim.x + threadIdx.x;
    if (e > M) return;
    if (e == M) { g_segptr[M] = Tn; return; }
    int lo = 0, hi = Tn;
    while (lo < hi) {
        int mid = (lo + hi) >> 1;
        if (st[mid] < e) lo = mid + 1; else hi = mid;
    }
    g_segptr[e] = lo;
}

// ---------------------------------------------------------------------------
// S[e,i,j] = sum_{t in seg(e)} cbf[t,i] * m_kt[id3_kt[t], j]
// one block per edge, 256 threads, syncless, software-pipelined
// ---------------------------------------------------------------------------
__global__ void k_bilS(const float* __restrict__ cbf, const int* __restrict__ id3_kt)
{
    const int e = blockIdx.x;
    const int tid = threadIdx.x;
    const int t0 = g_segptr[e], t1 = g_segptr[e + 1];
    const int i = tid >> 4;          // cbf index
    const int j = (tid & 15) * 4;    // tri index

    float4 acc = make_float4(0.f, 0.f, 0.f, 0.f);
    float  cv = 0.f;
    float4 mv = make_float4(0.f, 0.f, 0.f, 0.f);

    int t = t0;
    if (t < t1) {
        int kt = __ldg(&id3_kt[t]);
        cv = __ldg(&cbf[(size_t)t * 16 + i]);
        mv = *(const float4*)(g_mkt + (size_t)kt * 64 + j);
    }
    while (t < t1) {
        int tn = t + 1;
        float cv_n = 0.f;
        float4 mv_n = make_float4(0.f, 0.f, 0.f, 0.f);
        if (tn < t1) {
            int kt = __ldg(&id3_kt[tn]);
            cv_n = __ldg(&cbf[(size_t)tn * 16 + i]);
            mv_n = *(const float4*)(g_mkt + (size_t)kt * 64 + j);
        }
        acc.x = fmaf(cv, mv.x, acc.x);
        acc.y = fmaf(cv, mv.y, acc.y);
        acc.z = fmaf(cv, mv.z, acc.z);
        acc.w = fmaf(cv, mv.w, acc.w);
        cv = cv_n; mv = mv_n; t = tn;
    }
    *(float4*)(g_S + (size_t)e * 1024 + tid * 4) = acc;
}

// ---------------------------------------------------------------------------
// out[e,c] = (silu(x[e]@W_st[:,c]) + silu(x[idx_swap[e]]@W_ts[:,c])) / sqrt(2)
// ---------------------------------------------------------------------------
__global__ void k_out(const float* __restrict__ Wst, const float* __restrict__ Wts,
                      const int* __restrict__ idx_swap, float* __restrict__ out, int M)
{
    extern __shared__ float sm[];
    float* Xst = sm;                 // [64][65] (k-major, padded)
    float* Xgt = Xst + 64 * 65;      // [64][65]
    float* Ws  = Xgt + 64 * 65;      // [64][64]
    float* Wt  = Ws + 64 * 64;       // [64][64]
    const int tid = threadIdx.x;
    const int e0 = blockIdx.y * 64;
    const int col0 = blockIdx.x * 64;

    #pragma unroll
    for (int p = 0; p < 4; p++) {
        int l = p * 256 + tid;             // 0..1023
        int r = l >> 4, q = (l & 15) * 4;
        float4 v = *(const float4*)(g_x + (size_t)(e0 + r) * 64 + q);
        Xst[(q + 0) * 65 + r] = v.x; Xst[(q + 1) * 65 + r] = v.y;
        Xst[(q + 2) * 65 + r] = v.z; Xst[(q + 3) * 65 + r] = v.w;
        int ge = idx_swap[e0 + r];
        float4 g = *(const float4*)(g_x + (size_t)ge * 64 + q);
        Xgt[(q + 0) * 65 + r] = g.x; Xgt[(q + 1) * 65 + r] = g.y;
        Xgt[(q + 2) * 65 + r] = g.z; Xgt[(q + 3) * 65 + r] = g.w;
        *(float4*)&Ws[r * 64 + q] = *(const float4*)(Wst + (size_t)r * 512 + col0 + q);
        *(float4*)&Wt[r * 64 + q] = *(const float4*)(Wts + (size_t)r * 512 + col0 + q);
    }
    __syncthreads();

    const int tx = tid & 15, ty = tid >> 4;
    const int rb = ty * 4, cb = tx * 4;
    float accA[4][4] = {}, accB[4][4] = {};
    #pragma unroll
    for (int k = 0; k < 64; k++) {
        float q1[4], q2[4], b1[4], b2[4];
        #pragma unroll
        for (int i = 0; i < 4; i++) { q1[i] = Xst[k * 65 + rb + i]; q2[i] = Xgt[k * 65 + rb + i]; }
        #pragma unroll
        for (int j = 0; j < 4; j++) { b1[j] = Ws[k * 64 + cb + j]; b2[j] = Wt[k * 64 + cb + j]; }
        #pragma unroll
        for (int i = 0; i < 4; i++)
            #pragma unroll
            for (int j = 0; j < 4; j++) {
                accA[i][j] = fmaf(q1[i], b1[j], accA[i][j]);
                accB[i][j] = fmaf(q2[i], b2[j], accB[i][j]);
            }
    }

    const float inv_sqrt2 = 0.70710678118654752f;
    #pragma unroll
    for (int i = 0; i < 4; i++) {
        float4 o;
        o.x = (silu_f(accA[i][0]) + silu_f(accB[i][0])) * inv_sqrt2;
        o.y = (silu_f(accA[i][1]) + silu_f(accB[i][1])) * inv_sqrt2;
        o.z = (silu_f(accA[i][2]) + silu_f(accB[i][2])) * inv_sqrt2;
        o.w = (silu_f(accA[i][3]) + silu_f(accB[i][3])) * inv_sqrt2;
        *(float4*)(out + (size_t)(e0 + rb + i) * 512 + col0 + cb) = o;
    }
}

// ---------------------------------------------------------------------------
extern "C" void kernel_launch(void* const* d_in, const int* in_sizes, int n_in,
                              void* d_out, int out_size)
{
    const float* m_st     = (const float*)d_in[0];
    const float* rbf      = (const float*)d_in[1];
    const float* cbf      = (const float*)d_in[2];
    const int*   idx_swap = (const int*)  d_in[3];
    const int*   id3_kt   = (const int*)  d_in[4];
    const int*   id3_st   = (const int*)  d_in[5];
    /* d_in[6] = id3_ragged_idx (unused) */
    const float* W_mkt    = (const float*)d_in[7];
    const float* W_rbf    = (const float*)d_in[8];
    const float* W_down   = (const float*)d_in[9];
    const float* W_bil    = (const float*)d_in[10];
    const float* W_st     = (const float*)d_in[11];
    const float* W_ts     = (const float*)d_in[12];
    const float* s_rbf    = (const float*)d_in[13];
    const float* s_cbf    = (const float*)d_in[14];
    float* out = (float*)d_out;

    const int M  = in_sizes[0] / EMB_EDGE;   // 65536
    const int Tn = in_sizes[2] / EMB_CBF;    // 262144

    float *p_h1, *p_mkt, *p_S, *p_x;
    cudaGetSymbolAddress((void**)&p_h1,  g_h1);
    cudaGetSymbolAddress((void**)&p_mkt, g_mkt);
    cudaGetSymbolAddress((void**)&p_S,   g_S);
    cudaGetSymbolAddress((void**)&p_x,   g_x);

    // 1. h1 = silu(m_st @ W_mkt) * (rbf @ W_rbf) * s_rbf   [tf32 tensor cores]
    k_gemm1_tc<<<dim3(4, M / 128), 256>>>(m_st, W_mkt, rbf, W_rbf, s_rbf, p_h1, M);
    // 2. m_kt = silu(h1 @ W_down)
    k_gemm_n64<512, true, false><<<dim3(1, M / 128), 256>>>(p_h1, W_down, nullptr, p_mkt, M);
    // 3. segment pointers from sorted id3_st
    k_segptr<<<(M + 256) / 256, 256>>>(id3_st, Tn, M);
    // 4. S[e,i,j] = segment-sum of cbf outer m_t
    k_bilS<<<M, 256>>>(cbf, id3_kt);
    // 5. x = (S @ W_bil) * s_cbf
    k_gemm_n64<1024, false, true><<<dim3(1, M / 128), 256>>>(p_S, W_bil, s_cbf, p_x, M);
    // 6. out = (silu(x@W_st) + silu(x[swap]@W_ts)) / sqrt(2)
    cudaFuncSetAttribute(k_out, cudaFuncAttributeMaxDynamicSharedMemorySize, 66048);
    k_out<<<dim3(8, M / 64), 256, 66048>>>(W_st, W_ts, idx_swap, out, M);
}

// round 4
// speedup vs baseline: 2.0485x; 1.4450x over previous
#include <cuda_runtime.h>
#include <math.h>
#include <stdint.h>

#define EMB_EDGE 512
#define EMB_RBF  16
#define EMB_CBF  16
#define EMB_TRI  64
#define EMB_BIL  64
#define E_MAX    65536
#define T_MAX    262144

// scratch (device globals: allocation-free rule)
__device__ float g_h1[(size_t)E_MAX * EMB_EDGE];          // 128 MB
__device__ float g_mkt[(size_t)E_MAX * EMB_TRI];          // 16 MB
__device__ float g_x[(size_t)E_MAX * EMB_BIL];            // 16 MB
__device__ int   g_segptr[E_MAX + 1];

__device__ __forceinline__ float silu_f(float v) {
    return v / (1.0f + __expf(-v));
}

__device__ __forceinline__ uint32_t f2tf32(float f) {
    uint32_t u;
    asm("cvt.rna.tf32.f32 %0, %1;" : "=r"(u) : "f"(f));
    return u;
}

__device__ __forceinline__ void mma_tf32(float& d0, float& d1, float& d2, float& d3,
                                         uint32_t a0, uint32_t a1, uint32_t a2, uint32_t a3,
                                         uint32_t b0, uint32_t b1)
{
    asm volatile(
        "mma.sync.aligned.m16n8k8.row.col.f32.tf32.tf32.f32 "
        "{%0,%1,%2,%3}, {%4,%5,%6,%7}, {%8,%9}, {%0,%1,%2,%3};\n"
        : "+f"(d0), "+f"(d1), "+f"(d2), "+f"(d3)
        : "r"(a0), "r"(a1), "r"(a2), "r"(a3), "r"(b0), "r"(b1));
}

// ---------------------------------------------------------------------------
// Kernel 1 (tensor core, tf32):
//   h1 = silu(m_st @ W_mkt) * (rbf @ W_rbf) * s_rbf
// M x 512 x 512. Block tile 128x128, BK=32, 8 warps (4m x 2n), warp tile 32x64
// ---------------------------------------------------------------------------
#define A_PAD 36
#define B_PAD 136

__global__ void k_gemm1_tc(const float* __restrict__ A, const float* __restrict__ B,
                           const float* __restrict__ rbf, const float* __restrict__ Wr,
                           const float* __restrict__ s_rbf, float* __restrict__ C, int M)
{
    __shared__ __align__(16) char smem_raw[128 * A_PAD * 4 + 32 * B_PAD * 4];
    uint32_t* As = (uint32_t*)smem_raw;
    uint32_t* Bs = As + 128 * A_PAD;

    const int tid  = threadIdx.x;
    const int warp = tid >> 5;
    const int lane = tid & 31;
    const int grp  = lane >> 2;
    const int thr4 = lane & 3;
    const int warp_m = warp & 3;
    const int warp_n = warp >> 2;
    const int row0 = blockIdx.y * 128;
    const int col0 = blockIdx.x * 128;

    float acc[2][8][4];
    #pragma unroll
    for (int mi = 0; mi < 2; mi++)
        #pragma unroll
        for (int ni = 0; ni < 8; ni++)
            #pragma unroll
            for (int q = 0; q < 4; q++) acc[mi][ni][q] = 0.f;

    const int a_row = tid >> 3;
    const int a_kq  = (tid & 7) * 4;
    const int b_r   = tid >> 5;
    const int b_c   = (tid & 31) * 4;

    for (int k0 = 0; k0 < 512; k0 += 32) {
        #pragma unroll
        for (int p = 0; p < 4; p++) {
            int row = a_row + p * 32;
            float4 v = *(const float4*)(A + (size_t)(row0 + row) * 512 + k0 + a_kq);
            uint4 u = make_uint4(f2tf32(v.x), f2tf32(v.y), f2tf32(v.z), f2tf32(v.w));
            *(uint4*)(As + row * A_PAD + a_kq) = u;
        }
        #pragma unroll
        for (int p = 0; p < 4; p++) {
            int r = b_r + p * 8;
            float4 v = *(const float4*)(B + (size_t)(k0 + r) * 512 + col0 + b_c);
            uint4 u = make_uint4(f2tf32(v.x), f2tf32(v.y), f2tf32(v.z), f2tf32(v.w));
            *(uint4*)(Bs + r * B_PAD + b_c) = u;
        }
        __syncthreads();

        #pragma unroll
        for (int kk = 0; kk < 4; kk++) {
            const int k8 = kk * 8;
            uint32_t a[2][4], b[8][2];
            #pragma unroll
            for (int mi = 0; mi < 2; mi++) {
                int r = warp_m * 32 + mi * 16 + grp;
                a[mi][0] = As[(r    ) * A_PAD + k8 + thr4    ];
                a[mi][1] = As[(r + 8) * A_PAD + k8 + thr4    ];
                a[mi][2] = As[(r    ) * A_PAD + k8 + thr4 + 4];
                a[mi][3] = As[(r + 8) * A_PAD + k8 + thr4 + 4];
            }
            #pragma unroll
            for (int ni = 0; ni < 8; ni++) {
                int c = warp_n * 64 + ni * 8 + grp;
                b[ni][0] = Bs[(k8 + thr4    ) * B_PAD + c];
                b[ni][1] = Bs[(k8 + thr4 + 4) * B_PAD + c];
            }
            #pragma unroll
            for (int mi = 0; mi < 2; mi++)
                #pragma unroll
                for (int ni = 0; ni < 8; ni++)
                    mma_tf32(acc[mi][ni][0], acc[mi][ni][1], acc[mi][ni][2], acc[mi][ni][3],
                             a[mi][0], a[mi][1], a[mi][2], a[mi][3],
                             b[ni][0], b[ni][1]);
        }
        __syncthreads();
    }

    // epilogue: mod = rbf(128x16) @ Wr(16x128) in fp32
    float* rbf_s = (float*)smem_raw;            // [128][17]
    float* Wr_s  = rbf_s + 128 * 17;            // [16][132]
    {
        int r = tid >> 1, q0 = (tid & 1) * 8;
        float4 v0 = *(const float4*)(rbf + (size_t)(row0 + r) * 16 + q0);
        float4 v1 = *(const float4*)(rbf + (size_t)(row0 + r) * 16 + q0 + 4);
        rbf_s[r * 17 + q0 + 0] = v0.x; rbf_s[r * 17 + q0 + 1] = v0.y;
        rbf_s[r * 17 + q0 + 2] = v0.z; rbf_s[r * 17 + q0 + 3] = v0.w;
        rbf_s[r * 17 + q0 + 4] = v1.x; rbf_s[r * 17 + q0 + 5] = v1.y;
        rbf_s[r * 17 + q0 + 6] = v1.z; rbf_s[r * 17 + q0 + 7] = v1.w;
        int q = tid >> 4, c = (tid & 15) * 8;
        float4 w0 = *(const float4*)(Wr + (size_t)q * 512 + col0 + c);
        float4 w1 = *(const float4*)(Wr + (size_t)q * 512 + col0 + c + 4);
        *(float4*)(Wr_s + q * 132 + c)     = w0;
        *(float4*)(Wr_s + q * 132 + c + 4) = w1;
    }
    __syncthreads();

    const float s = *s_rbf;
    #pragma unroll
    for (int mi = 0; mi < 2; mi++) {
        int r_lo = warp_m * 32 + mi * 16 + grp;
        int r_hi = r_lo + 8;
        float rlo[16], rhi[16];
        #pragma unroll
        for (int q = 0; q < 16; q++) {
            rlo[q] = rbf_s[r_lo * 17 + q];
            rhi[q] = rbf_s[r_hi * 17 + q];
        }
        #pragma unroll
        for (int ni = 0; ni < 8; ni++) {
            int c_s = warp_n * 64 + ni * 8 + thr4 * 2;
            float m00 = 0.f, m01 = 0.f, m10 = 0.f, m11 = 0.f;
            #pragma unroll
            for (int q = 0; q < 16; q++) {
                float w0 = Wr_s[q * 132 + c_s];
                float w1 = Wr_s[q * 132 + c_s + 1];
                m00 = fmaf(rlo[q], w0, m00); m01 = fmaf(rlo[q], w1, m01);
                m10 = fmaf(rhi[q], w0, m10); m11 = fmaf(rhi[q], w1, m11);
            }
            float2 o_lo, o_hi;
            o_lo.x = silu_f(acc[mi][ni][0]) * m00 * s;
            o_lo.y = silu_f(acc[mi][ni][1]) * m01 * s;
            o_hi.x = silu_f(acc[mi][ni][2]) * m10 * s;
            o_hi.y = silu_f(acc[mi][ni][3]) * m11 * s;
            *(float2*)(C + (size_t)(row0 + r_lo) * 512 + col0 + c_s) = o_lo;
            *(float2*)(C + (size_t)(row0 + r_hi) * 512 + col0 + c_s) = o_hi;
        }
    }
}

// ---------------------------------------------------------------------------
// Kernel 2 (tensor core, tf32): m_kt = silu(h1 @ W_down)
// M x 512 x 64. BM=128 BK=32, 8 warps (each warp: 16 rows x 64 cols)
// ---------------------------------------------------------------------------
__global__ void k_gemm2_tc(const float* __restrict__ A, const float* __restrict__ B,
                           float* __restrict__ C, int M)
{
    __shared__ __align__(16) uint32_t As[128 * A_PAD];  // [128][36]
    __shared__ __align__(16) uint32_t Bs[32 * 72];      // [32][72]

    const int tid  = threadIdx.x;
    const int warp = tid >> 5;       // = warp_m (16 rows each)
    const int lane = tid & 31;
    const int grp  = lane >> 2;
    const int thr4 = lane & 3;
    const int row0 = blockIdx.y * 128;

    float acc[8][4];
    #pragma unroll
    for (int ni = 0; ni < 8; ni++)
        #pragma unroll
        for (int q = 0; q < 4; q++) acc[ni][q] = 0.f;

    const int a_row = tid >> 3;
    const int a_kq  = (tid & 7) * 4;

    for (int k0 = 0; k0 < 512; k0 += 32) {
        #pragma unroll
        for (int p = 0; p < 4; p++) {
            int row = a_row + p * 32;
            float4 v = *(const float4*)(A + (size_t)(row0 + row) * 512 + k0 + a_kq);
            uint4 u = make_uint4(f2tf32(v.x), f2tf32(v.y), f2tf32(v.z), f2tf32(v.w));
            *(uint4*)(As + row * A_PAD + a_kq) = u;
        }
        #pragma unroll
        for (int p = 0; p < 2; p++) {
            int idx = p * 256 + tid;             // 0..511
            int r = idx >> 4, c = (idx & 15) * 4;
            float4 v = *(const float4*)(B + (size_t)(k0 + r) * 64 + c);
            uint4 u = make_uint4(f2tf32(v.x), f2tf32(v.y), f2tf32(v.z), f2tf32(v.w));
            *(uint4*)(Bs + r * 72 + c) = u;
        }
        __syncthreads();

        #pragma unroll
        for (int kk = 0; kk < 4; kk++) {
            const int k8 = kk * 8;
            int r = warp * 16 + grp;
            uint32_t a0 = As[(r    ) * A_PAD + k8 + thr4    ];
            uint32_t a1 = As[(r + 8) * A_PAD + k8 + thr4    ];
            uint32_t a2 = As[(r    ) * A_PAD + k8 + thr4 + 4];
            uint32_t a3 = As[(r + 8) * A_PAD + k8 + thr4 + 4];
            #pragma unroll
            for (int ni = 0; ni < 8; ni++) {
                uint32_t b0 = Bs[(k8 + thr4    ) * 72 + ni * 8 + grp];
                uint32_t b1 = Bs[(k8 + thr4 + 4) * 72 + ni * 8 + grp];
                mma_tf32(acc[ni][0], acc[ni][1], acc[ni][2], acc[ni][3],
                         a0, a1, a2, a3, b0, b1);
            }
        }
        __syncthreads();
    }

    int r_lo = row0 + warp * 16 + grp;
    int r_hi = r_lo + 8;
    #pragma unroll
    for (int ni = 0; ni < 8; ni++) {
        int c = ni * 8 + thr4 * 2;
        float2 o_lo = make_float2(silu_f(acc[ni][0]), silu_f(acc[ni][1]));
        float2 o_hi = make_float2(silu_f(acc[ni][2]), silu_f(acc[ni][3]));
        *(float2*)(C + (size_t)r_lo * 64 + c) = o_lo;
        *(float2*)(C + (size_t)r_hi * 64 + c) = o_hi;
    }
}

// ---------------------------------------------------------------------------
// segment pointers: seg_ptr[e] = lower_bound(id3_st, e); seg_ptr[M] = T
// ---------------------------------------------------------------------------
__global__ void k_segptr(const int* __restrict__ st, int Tn, int M)
{
    int e = blockIdx.x * blockDim.x + threadIdx.x;
    if (e > M) return;
    if (e == M) { g_segptr[M] = Tn; return; }
    int lo = 0, hi = Tn;
    while (lo < hi) {
        int mid = (lo + hi) >> 1;
        if (st[mid] < e) lo = mid + 1; else hi = mid;
    }
    g_segptr[e] = lo;
}

// ---------------------------------------------------------------------------
// Fused bilinear: x[e,:] = (segment_sum_t(cbf[t] outer m_kt[kt]) flattened
//                          @ W_bil(1024x64)) * s_cbf
// Block = 16 edges, 8 warps.
// Phase 1: warp w computes S for edges w*2, w*2+1 in regs -> smem Z (tf32)
// Phase 2: Z(16x1024) @ W_bil via m16n8k8, warp w owns 8 output cols
// ---------------------------------------------------------------------------
__global__ void k_bilx(const float* __restrict__ cbf, const int* __restrict__ id3_kt,
                       const float* __restrict__ Wb, const float* __restrict__ s_cbf,
                       float* __restrict__ X)
{
    extern __shared__ __align__(16) uint32_t Zu[];   // [16][1028]
    const int tid  = threadIdx.x;
    const int warp = tid >> 5;
    const int lane = tid & 31;
    const int grp  = lane >> 2;
    const int thr4 = lane & 3;
    const int e0 = blockIdx.x * 16;

    // ---- phase 1: per-edge segment sums ----
    #pragma unroll
    for (int sub = 0; sub < 2; sub++) {
        const int eloc = warp * 2 + sub;
        const int e = e0 + eloc;
        const int t0 = g_segptr[e], t1 = g_segptr[e + 1];
        float acc[16][2];
        #pragma unroll
        for (int i = 0; i < 16; i++) { acc[i][0] = 0.f; acc[i][1] = 0.f; }

        for (int t = t0; t < t1; t++) {
            int kt = __ldg(&id3_kt[t]);
            float cval = (lane < 16) ? __ldg(&cbf[(size_t)t * 16 + lane]) : 0.f;
            float2 m2 = *(const float2*)(g_mkt + (size_t)kt * 64 + lane * 2);
            #pragma unroll
            for (int i = 0; i < 16; i++) {
                float ci = __shfl_sync(0xFFFFFFFFu, cval, i);
                acc[i][0] = fmaf(ci, m2.x, acc[i][0]);
                acc[i][1] = fmaf(ci, m2.y, acc[i][1]);
            }
        }
        #pragma unroll
        for (int i = 0; i < 16; i++) {
            uint2 u = make_uint2(f2tf32(acc[i][0]), f2tf32(acc[i][1]));
            *(uint2*)(Zu + eloc * 1028 + i * 64 + lane * 2) = u;
        }
    }
    __syncthreads();

    // ---- phase 2: Z(16x1024) @ Wb(1024x64), warp w -> cols [w*8, w*8+8) ----
    const int n0 = warp * 8;
    float c0 = 0.f, c1 = 0.f, c2 = 0.f, c3 = 0.f;
    #pragma unroll 4
    for (int k8 = 0; k8 < 1024; k8 += 8) {
        uint32_t a0 = Zu[(grp    ) * 1028 + k8 + thr4    ];
        uint32_t a1 = Zu[(grp + 8) * 1028 + k8 + thr4    ];
        uint32_t a2 = Zu[(grp    ) * 1028 + k8 + thr4 + 4];
        uint32_t a3 = Zu[(grp + 8) * 1028 + k8 + thr4 + 4];
        uint32_t b0 = f2tf32(__ldg(&Wb[(size_t)(k8 + thr4    ) * 64 + n0 + grp]));
        uint32_t b1 = f2tf32(__ldg(&Wb[(size_t)(k8 + thr4 + 4) * 64 + n0 + grp]));
        mma_tf32(c0, c1, c2, c3, a0, a1, a2, a3, b0, b1);
    }

    const float sc = *s_cbf;
    int col = n0 + thr4 * 2;
    *(float2*)(X + (size_t)(e0 + grp    ) * 64 + col) = make_float2(c0 * sc, c1 * sc);
    *(float2*)(X + (size_t)(e0 + grp + 8) * 64 + col) = make_float2(c2 * sc, c3 * sc);
}

// ---------------------------------------------------------------------------
// Output (tensor core, tf32):
// out[e,c] = (silu(x[e]@W_st[:,c]) + silu(x[idx_swap[e]]@W_ts[:,c])) / sqrt(2)
// BM=64 edges, BN=128 cols, K=64 in smem. 8 warps (4m x 2n).
// ---------------------------------------------------------------------------
__global__ void __launch_bounds__(256, 2)
k_out_tc(const float* __restrict__ Wst, const float* __restrict__ Wts,
         const int* __restrict__ idx_swap, const float* __restrict__ X,
         float* __restrict__ out, int M)
{
    extern __shared__ __align__(16) uint32_t sm_u[];
    uint32_t* X1s = sm_u;                 // [64][68]
    uint32_t* X2s = X1s + 64 * 68;        // [64][68]
    uint32_t* W1s = X2s + 64 * 68;        // [64][136]
    uint32_t* W2s = W1s + 64 * 136;       // [64][136]

    const int tid  = threadIdx.x;
    const int warp = tid >> 5;
    const int lane = tid & 31;
    const int grp  = lane >> 2;
    const int thr4 = lane & 3;
    const int warp_m = warp & 3;
    const int warp_n = warp >> 2;
    const int e0 = blockIdx.y * 64;
    const int col0 = blockIdx.x * 128;

    // load X rows (direct + swapped)
    #pragma unroll
    for (int p = 0; p < 4; p++) {
        int idx = p * 256 + tid;              // 0..1023
        int r = idx >> 4, q = (idx & 15) * 4;
        float4 v = *(const float4*)(X + (size_t)(e0 + r) * 64 + q);
        *(uint4*)(X1s + r * 68 + q) =
            make_uint4(f2tf32(v.x), f2tf32(v.y), f2tf32(v.z), f2tf32(v.w));
        int ge = __ldg(&idx_swap[e0 + r]);
        float4 g = *(const float4*)(X + (size_t)ge * 64 + q);
        *(uint4*)(X2s + r * 68 + q) =
            make_uint4(f2tf32(g.x), f2tf32(g.y), f2tf32(g.z), f2tf32(g.w));
    }
    // load W tiles (64 x 128 each)
    #pragma unroll
    for (int p = 0; p < 8; p++) {
        int idx = p * 256 + tid;              // 0..2047
        int r = idx >> 5, c4 = (idx & 31) * 4;
        float4 v1 = *(const float4*)(Wst + (size_t)r * 512 + col0 + c4);
        *(uint4*)(W1s + r * 136 + c4) =
            make_uint4(f2tf32(v1.x), f2tf32(v1.y), f2tf32(v1.z), f2tf32(v1.w));
        float4 v2 = *(const float4*)(Wts + (size_t)r * 512 + col0 + c4);
        *(uint4*)(W2s + r * 136 + c4) =
            make_uint4(f2tf32(v2.x), f2tf32(v2.y), f2tf32(v2.z), f2tf32(v2.w));
    }
    __syncthreads();

    float accA[8][4], accB[8][4];
    #pragma unroll
    for (int ni = 0; ni < 8; ni++)
        #pragma unroll
        for (int q = 0; q < 4; q++) { accA[ni][q] = 0.f; accB[ni][q] = 0.f; }

    const int rA = warp_m * 16 + grp;
    #pragma unroll
    for (int k8 = 0; k8 < 64; k8 += 8) {
        uint32_t a1[4], a2[4];
        a1[0] = X1s[(rA    ) * 68 + k8 + thr4    ];
        a1[1] = X1s[(rA + 8) * 68 + k8 + thr4    ];
        a1[2] = X1s[(rA    ) * 68 + k8 + thr4 + 4];
        a1[3] = X1s[(rA + 8) * 68 + k8 + thr4 + 4];
        a2[0] = X2s[(rA    ) * 68 + k8 + thr4    ];
        a2[1] = X2s[(rA + 8) * 68 + k8 + thr4    ];
        a2[2] = X2s[(rA    ) * 68 + k8 + thr4 + 4];
        a2[3] = X2s[(rA + 8) * 68 + k8 + thr4 + 4];
        #pragma unroll
        for (int ni = 0; ni < 8; ni++) {
            int c = warp_n * 64 + ni * 8 + grp;
            uint32_t b10 = W1s[(k8 + thr4    ) * 136 + c];
            uint32_t b11 = W1s[(k8 + thr4 + 4) * 136 + c];
            uint32_t b20 = W2s[(k8 + thr4    ) * 136 + c];
            uint32_t b21 = W2s[(k8 + thr4 + 4) * 136 + c];
            mma_tf32(accA[ni][0], accA[ni][1], accA[ni][2], accA[ni][3],
                     a1[0], a1[1], a1[2], a1[3], b10, b11);
            mma_tf32(accB[ni][0], accB[ni][1], accB[ni][2], accB[ni][3],
                     a2[0], a2[1], a2[2], a2[3], b20, b21);
        }
    }

    const float inv_sqrt2 = 0.70710678118654752f;
    int r_lo = e0 + warp_m * 16 + grp;
    int r_hi = r_lo + 8;
    #pragma unroll
    for (int ni = 0; ni < 8; ni++) {
        int c = col0 + warp_n * 64 + ni * 8 + thr4 * 2;
        float2 o_lo, o_hi;
        o_lo.x = (silu_f(accA[ni][0]) + silu_f(accB[ni][0])) * inv_sqrt2;
        o_lo.y = (silu_f(accA[ni][1]) + silu_f(accB[ni][1])) * inv_sqrt2;
        o_hi.x = (silu_f(accA[ni][2]) + silu_f(accB[ni][2])) * inv_sqrt2;
        o_hi.y = (silu_f(accA[ni][3]) + silu_f(accB[ni][3])) * inv_sqrt2;
        *(float2*)(out + (size_t)r_lo * 512 + c) = o_lo;
        *(float2*)(out + (size_t)r_hi * 512 + c) = o_hi;
    }
}

// ---------------------------------------------------------------------------
extern "C" void kernel_launch(void* const* d_in, const int* in_sizes, int n_in,
                              void* d_out, int out_size)
{
    const float* m_st     = (const float*)d_in[0];
    const float* rbf      = (const float*)d_in[1];
    const float* cbf      = (const float*)d_in[2];
    const int*   idx_swap = (const int*)  d_in[3];
    const int*   id3_kt   = (const int*)  d_in[4];
    const int*   id3_st   = (const int*)  d_in[5];
    /* d_in[6] = id3_ragged_idx (unused) */
    const float* W_mkt    = (const float*)d_in[7];
    const float* W_rbf    = (const float*)d_in[8];
    const float* W_down   = (const float*)d_in[9];
    const float* W_bil    = (const float*)d_in[10];
    const float* W_st     = (const float*)d_in[11];
    const float* W_ts     = (const float*)d_in[12];
    const float* s_rbf    = (const float*)d_in[13];
    const float* s_cbf    = (const float*)d_in[14];
    float* out = (float*)d_out;

    const int M  = in_sizes[0] / EMB_EDGE;   // 65536
    const int Tn = in_sizes[2] / EMB_CBF;    // 262144

    float *p_h1, *p_mkt, *p_x;
    cudaGetSymbolAddress((void**)&p_h1,  g_h1);
    cudaGetSymbolAddress((void**)&p_mkt, g_mkt);
    cudaGetSymbolAddress((void**)&p_x,   g_x);

    // 1. h1 = silu(m_st @ W_mkt) * (rbf @ W_rbf) * s_rbf   [tf32]
    k_gemm1_tc<<<dim3(4, M / 128), 256>>>(m_st, W_mkt, rbf, W_rbf, s_rbf, p_h1, M);
    // 2. m_kt = silu(h1 @ W_down)                          [tf32]
    k_gemm2_tc<<<dim3(1, M / 128), 256>>>(p_h1, W_down, p_mkt, M);
    // 3. segment pointers from sorted id3_st
    k_segptr<<<(M + 256) / 256, 256>>>(id3_st, Tn, M);
    // 4+5 fused: x = (segment_sum(cbf outer m_t) @ W_bil) * s_cbf   [tf32]
    {
        const int smem = 16 * 1028 * 4;   // 65792 B
        cudaFuncSetAttribute(k_bilx, cudaFuncAttributeMaxDynamicSharedMemorySize, smem);
        k_bilx<<<M / 16, 256, smem>>>(cbf, id3_kt, W_bil, s_cbf, p_x);
    }
    // 6. out = (silu(x@W_st) + silu(x[swap]@W_ts)) / sqrt(2)   [tf32]
    {
        const int smem = (2 * 64 * 68 + 2 * 64 * 136) * 4;   // 104448 B
        cudaFuncSetAttribute(k_out_tc, cudaFuncAttributeMaxDynamicSharedMemorySize, smem);
        k_out_tc<<<dim3(4, M / 64), 256, smem>>>(W_st, W_ts, idx_swap, p_x, out, M);
    }
}

// round 5
// speedup vs baseline: 2.2385x; 1.0928x over previous
#include <cuda_runtime.h>
#include <math.h>
#include <stdint.h>

#define EMB_EDGE 512
#define EMB_RBF  16
#define EMB_CBF  16
#define EMB_TRI  64
#define EMB_BIL  64
#define E_MAX    65536
#define T_MAX    262144

// scratch (device globals: allocation-free rule)
__device__ float g_h1[(size_t)E_MAX * EMB_EDGE];          // 128 MB
__device__ float g_mkt[(size_t)E_MAX * EMB_TRI];          // 16 MB
__device__ float g_x[(size_t)E_MAX * EMB_BIL];            // 16 MB
__device__ int   g_segptr[E_MAX + 1];

__device__ __forceinline__ float silu_f(float v) {
    return v / (1.0f + __expf(-v));
}

__device__ __forceinline__ uint32_t f2tf32(float f) {
    uint32_t u;
    asm("cvt.rna.tf32.f32 %0, %1;" : "=r"(u) : "f"(f));
    return u;
}

__device__ __forceinline__ void mma_tf32(float& d0, float& d1, float& d2, float& d3,
                                         uint32_t a0, uint32_t a1, uint32_t a2, uint32_t a3,
                                         uint32_t b0, uint32_t b1)
{
    asm volatile(
        "mma.sync.aligned.m16n8k8.row.col.f32.tf32.tf32.f32 "
        "{%0,%1,%2,%3}, {%4,%5,%6,%7}, {%8,%9}, {%0,%1,%2,%3};\n"
        : "+f"(d0), "+f"(d1), "+f"(d2), "+f"(d3)
        : "r"(a0), "r"(a1), "r"(a2), "r"(a3), "r"(b0), "r"(b1));
}

#define CP_ASYNC16(dst_u32, src_ptr) \
    asm volatile("cp.async.ca.shared.global [%0], [%1], 16;" :: "r"(dst_u32), "l"(src_ptr))
#define CP_COMMIT() asm volatile("cp.async.commit_group;")
#define CP_WAIT1()  asm volatile("cp.async.wait_group 1;")
#define CP_WAIT0()  asm volatile("cp.async.wait_group 0;")

// ---------------------------------------------------------------------------
// Kernel 1 (tensor core, tf32, 2-stage cp.async pipeline):
//   h1 = silu(m_st @ W_mkt) * (rbf @ W_rbf) * s_rbf
// M x 512 x 512. Block tile 128x128, BK=32, 8 warps (4m x 2n), warp tile 32x64
// smem holds raw fp32; cvt->tf32 at fragment-load time.
// ---------------------------------------------------------------------------
#define A_PAD 36
#define B_PAD 136
#define G1_AS (128 * A_PAD)        // 4608 floats
#define G1_BS (32 * B_PAD)         // 4352 floats
#define G1_STAGE (G1_AS + G1_BS)   // 8960 floats
#define G1_SMEM (2 * G1_STAGE * 4) // 71680 bytes

__device__ __forceinline__ void g1_load_stage(float* As, float* Bs,
                                              const float* __restrict__ A,
                                              const float* __restrict__ B,
                                              int row0, int col0, int k0, int tid)
{
    const int a_row = tid >> 3, a_kq = (tid & 7) * 4;
    #pragma unroll
    for (int p = 0; p < 4; p++) {
        int row = a_row + p * 32;
        uint32_t d = (uint32_t)__cvta_generic_to_shared(As + row * A_PAD + a_kq);
        CP_ASYNC16(d, A + (size_t)(row0 + row) * 512 + k0 + a_kq);
    }
    const int b_r = tid >> 5, b_c = (tid & 31) * 4;
    #pragma unroll
    for (int p = 0; p < 4; p++) {
        int r = b_r + p * 8;
        uint32_t d = (uint32_t)__cvta_generic_to_shared(Bs + r * B_PAD + b_c);
        CP_ASYNC16(d, B + (size_t)(k0 + r) * 512 + col0 + b_c);
    }
}

__global__ void __launch_bounds__(256, 2)
k_gemm1_tc(const float* __restrict__ A, const float* __restrict__ B,
           const float* __restrict__ rbf, const float* __restrict__ Wr,
           const float* __restrict__ s_rbf, float* __restrict__ C, int M)
{
    extern __shared__ __align__(16) float sm_g1[];
    float* AsBuf[2] = { sm_g1, sm_g1 + G1_STAGE };

    const int tid  = threadIdx.x;
    const int warp = tid >> 5;
    const int lane = tid & 31;
    const int grp  = lane >> 2;
    const int thr4 = lane & 3;
    const int warp_m = warp & 3;
    const int warp_n = warp >> 2;
    const int row0 = blockIdx.y * 128;
    const int col0 = blockIdx.x * 128;

    float acc[2][8][4];
    #pragma unroll
    for (int mi = 0; mi < 2; mi++)
        #pragma unroll
        for (int ni = 0; ni < 8; ni++)
            #pragma unroll
            for (int q = 0; q < 4; q++) acc[mi][ni][q] = 0.f;

    g1_load_stage(AsBuf[0], AsBuf[0] + G1_AS, A, B, row0, col0, 0, tid);
    CP_COMMIT();

    #pragma unroll 1
    for (int it = 0; it < 16; it++) {
        const int buf = it & 1;
        if (it + 1 < 16) {
            g1_load_stage(AsBuf[buf ^ 1], AsBuf[buf ^ 1] + G1_AS, A, B,
                          row0, col0, (it + 1) * 32, tid);
            CP_COMMIT();
            CP_WAIT1();
        } else {
            CP_WAIT0();
        }
        __syncthreads();

        const float* Asf = AsBuf[buf];
        const float* Bsf = AsBuf[buf] + G1_AS;
        #pragma unroll
        for (int kk = 0; kk < 4; kk++) {
            const int k8 = kk * 8;
            uint32_t a[2][4], b[8][2];
            #pragma unroll
            for (int mi = 0; mi < 2; mi++) {
                int r = warp_m * 32 + mi * 16 + grp;
                a[mi][0] = f2tf32(Asf[(r    ) * A_PAD + k8 + thr4    ]);
                a[mi][1] = f2tf32(Asf[(r + 8) * A_PAD + k8 + thr4    ]);
                a[mi][2] = f2tf32(Asf[(r    ) * A_PAD + k8 + thr4 + 4]);
                a[mi][3] = f2tf32(Asf[(r + 8) * A_PAD + k8 + thr4 + 4]);
            }
            #pragma unroll
            for (int ni = 0; ni < 8; ni++) {
                int c = warp_n * 64 + ni * 8 + grp;
                b[ni][0] = f2tf32(Bsf[(k8 + thr4    ) * B_PAD + c]);
                b[ni][1] = f2tf32(Bsf[(k8 + thr4 + 4) * B_PAD + c]);
            }
            #pragma unroll
            for (int mi = 0; mi < 2; mi++)
                #pragma unroll
                for (int ni = 0; ni < 8; ni++)
                    mma_tf32(acc[mi][ni][0], acc[mi][ni][1], acc[mi][ni][2], acc[mi][ni][3],
                             a[mi][0], a[mi][1], a[mi][2], a[mi][3],
                             b[ni][0], b[ni][1]);
        }
        __syncthreads();
    }

    // epilogue: mod = rbf(128x16) @ Wr(16x128) in fp32
    float* rbf_s = sm_g1;                 // [128][17]
    float* Wr_s  = rbf_s + 128 * 17;      // [16][132]
    {
        int r = tid >> 1, q0 = (tid & 1) * 8;
        float4 v0 = *(const float4*)(rbf + (size_t)(row0 + r) * 16 + q0);
        float4 v1 = *(const float4*)(rbf + (size_t)(row0 + r) * 16 + q0 + 4);
        rbf_s[r * 17 + q0 + 0] = v0.x; rbf_s[r * 17 + q0 + 1] = v0.y;
        rbf_s[r * 17 + q0 + 2] = v0.z; rbf_s[r * 17 + q0 + 3] = v0.w;
        rbf_s[r * 17 + q0 + 4] = v1.x; rbf_s[r * 17 + q0 + 5] = v1.y;
        rbf_s[r * 17 + q0 + 6] = v1.z; rbf_s[r * 17 + q0 + 7] = v1.w;
        int q = tid >> 4, c = (tid & 15) * 8;
        float4 w0 = *(const float4*)(Wr + (size_t)q * 512 + col0 + c);
        float4 w1 = *(const float4*)(Wr + (size_t)q * 512 + col0 + c + 4);
        *(float4*)(Wr_s + q * 132 + c)     = w0;
        *(float4*)(Wr_s + q * 132 + c + 4) = w1;
    }
    __syncthreads();

    const float s = *s_rbf;
    #pragma unroll
    for (int mi = 0; mi < 2; mi++) {
        int r_lo = warp_m * 32 + mi * 16 + grp;
        int r_hi = r_lo + 8;
        float rlo[16], rhi[16];
        #pragma unroll
        for (int q = 0; q < 16; q++) {
            rlo[q] = rbf_s[r_lo * 17 + q];
            rhi[q] = rbf_s[r_hi * 17 + q];
        }
        #pragma unroll
        for (int ni = 0; ni < 8; ni++) {
            int c_s = warp_n * 64 + ni * 8 + thr4 * 2;
            float m00 = 0.f, m01 = 0.f, m10 = 0.f, m11 = 0.f;
            #pragma unroll
            for (int q = 0; q < 16; q++) {
                float w0 = Wr_s[q * 132 + c_s];
                float w1 = Wr_s[q * 132 + c_s + 1];
                m00 = fmaf(rlo[q], w0, m00); m01 = fmaf(rlo[q], w1, m01);
                m10 = fmaf(rhi[q], w0, m10); m11 = fmaf(rhi[q], w1, m11);
            }
            float2 o_lo, o_hi;
            o_lo.x = silu_f(acc[mi][ni][0]) * m00 * s;
            o_lo.y = silu_f(acc[mi][ni][1]) * m01 * s;
            o_hi.x = silu_f(acc[mi][ni][2]) * m10 * s;
            o_hi.y = silu_f(acc[mi][ni][3]) * m11 * s;
            *(float2*)(C + (size_t)(row0 + r_lo) * 512 + col0 + c_s) = o_lo;
            *(float2*)(C + (size_t)(row0 + r_hi) * 512 + col0 + c_s) = o_hi;
        }
    }
}

// ---------------------------------------------------------------------------
// Kernel 2 (tensor core, tf32): m_kt = silu(h1 @ W_down)
// M x 512 x 64. BM=128 BK=32, 8 warps (each warp: 16 rows x 64 cols)
// ---------------------------------------------------------------------------
__global__ void k_gemm2_tc(const float* __restrict__ A, const float* __restrict__ B,
                           float* __restrict__ C, int M)
{
    __shared__ __align__(16) uint32_t As[128 * A_PAD];  // [128][36]
    __shared__ __align__(16) uint32_t Bs[32 * 72];      // [32][72]

    const int tid  = threadIdx.x;
    const int warp = tid >> 5;
    const int lane = tid & 31;
    const int grp  = lane >> 2;
    const int thr4 = lane & 3;
    const int row0 = blockIdx.y * 128;

    float acc[8][4];
    #pragma unroll
    for (int ni = 0; ni < 8; ni++)
        #pragma unroll
        for (int q = 0; q < 4; q++) acc[ni][q] = 0.f;

    const int a_row = tid >> 3;
    const int a_kq  = (tid & 7) * 4;

    for (int k0 = 0; k0 < 512; k0 += 32) {
        #pragma unroll
        for (int p = 0; p < 4; p++) {
            int row = a_row + p * 32;
            float4 v = *(const float4*)(A + (size_t)(row0 + row) * 512 + k0 + a_kq);
            uint4 u = make_uint4(f2tf32(v.x), f2tf32(v.y), f2tf32(v.z), f2tf32(v.w));
            *(uint4*)(As + row * A_PAD + a_kq) = u;
        }
        #pragma unroll
        for (int p = 0; p < 2; p++) {
            int idx = p * 256 + tid;             // 0..511
            int r = idx >> 4, c = (idx & 15) * 4;
            float4 v = *(const float4*)(B + (size_t)(k0 + r) * 64 + c);
            uint4 u = make_uint4(f2tf32(v.x), f2tf32(v.y), f2tf32(v.z), f2tf32(v.w));
            *(uint4*)(Bs + r * 72 + c) = u;
        }
        __syncthreads();

        #pragma unroll
        for (int kk = 0; kk < 4; kk++) {
            const int k8 = kk * 8;
            int r = warp * 16 + grp;
            uint32_t a0 = As[(r    ) * A_PAD + k8 + thr4    ];
            uint32_t a1 = As[(r + 8) * A_PAD + k8 + thr4    ];
            uint32_t a2 = As[(r    ) * A_PAD + k8 + thr4 + 4];
            uint32_t a3 = As[(r + 8) * A_PAD + k8 + thr4 + 4];
            #pragma unroll
            for (int ni = 0; ni < 8; ni++) {
                uint32_t b0 = Bs[(k8 + thr4    ) * 72 + ni * 8 + grp];
                uint32_t b1 = Bs[(k8 + thr4 + 4) * 72 + ni * 8 + grp];
                mma_tf32(acc[ni][0], acc[ni][1], acc[ni][2], acc[ni][3],
                         a0, a1, a2, a3, b0, b1);
            }
        }
        __syncthreads();
    }

    int r_lo = row0 + warp * 16 + grp;
    int r_hi = r_lo + 8;
    #pragma unroll
    for (int ni = 0; ni < 8; ni++) {
        int c = ni * 8 + thr4 * 2;
        float2 o_lo = make_float2(silu_f(acc[ni][0]), silu_f(acc[ni][1]));
        float2 o_hi = make_float2(silu_f(acc[ni][2]), silu_f(acc[ni][3]));
        *(float2*)(C + (size_t)r_lo * 64 + c) = o_lo;
        *(float2*)(C + (size_t)r_hi * 64 + c) = o_hi;
    }
}

// ---------------------------------------------------------------------------
// segment pointers: seg_ptr[e] = lower_bound(id3_st, e); seg_ptr[M] = T
// ---------------------------------------------------------------------------
__global__ void k_segptr(const int* __restrict__ st, int Tn, int M)
{
    int e = blockIdx.x * blockDim.x + threadIdx.x;
    if (e > M) return;
    if (e == M) { g_segptr[M] = Tn; return; }
    int lo = 0, hi = Tn;
    while (lo < hi) {
        int mid = (lo + hi) >> 1;
        if (st[mid] < e) lo = mid + 1; else hi = mid;
    }
    g_segptr[e] = lo;
}

// ---------------------------------------------------------------------------
// Fused bilinear: x[e,:] = (segment_sum_t(cbf[t] outer m_kt[kt]) flattened
//                          @ W_bil(1024x64)) * s_cbf
// Block = 16 edges, 8 warps.
// Phase 1: warp w computes S for edges w*2, w*2+1 in regs -> smem Z (tf32)
// Phase 2: K-SPLIT — warp w takes K slice [w*128,(w+1)*128), computes full
//          16x64 partial via m16n8k8, writes to smem; then 8-way reduction.
// ---------------------------------------------------------------------------
#define BILX_Z   (16 * 1028)                 // uint32 elems
#define BILX_P   (8 * 16 * 68)               // float elems (padded partials)
#define BILX_SMEM ((BILX_Z + BILX_P) * 4)    // 100608 bytes

__global__ void __launch_bounds__(256, 2)
k_bilx(const float* __restrict__ cbf, const int* __restrict__ id3_kt,
       const float* __restrict__ Wb, const float* __restrict__ s_cbf,
       float* __restrict__ X)
{
    extern __shared__ __align__(16) uint32_t sm_bx[];
    uint32_t* Zu = sm_bx;                    // [16][1028] tf32
    float*    Ps = (float*)(sm_bx + BILX_Z); // [8][16][68] fp32 partials

    const int tid  = threadIdx.x;
    const int warp = tid >> 5;
    const int lane = tid & 31;
    const int grp  = lane >> 2;
    const int thr4 = lane & 3;
    const int e0 = blockIdx.x * 16;

    // ---- phase 1: per-edge segment sums (warp w -> edges w*2, w*2+1) ----
    #pragma unroll
    for (int sub = 0; sub < 2; sub++) {
        const int eloc = warp * 2 + sub;
        const int e = e0 + eloc;
        const int t0 = g_segptr[e], t1 = g_segptr[e + 1];
        float acc[16][2];
        #pragma unroll
        for (int i = 0; i < 16; i++) { acc[i][0] = 0.f; acc[i][1] = 0.f; }

        for (int t = t0; t < t1; t++) {
            int kt = __ldg(&id3_kt[t]);
            float cval = (lane < 16) ? __ldg(&cbf[(size_t)t * 16 + lane]) : 0.f;
            float2 m2 = *(const float2*)(g_mkt + (size_t)kt * 64 + lane * 2);
            #pragma unroll
            for (int i = 0; i < 16; i++) {
                float ci = __shfl_sync(0xFFFFFFFFu, cval, i);
                acc[i][0] = fmaf(ci, m2.x, acc[i][0]);
                acc[i][1] = fmaf(ci, m2.y, acc[i][1]);
            }
        }
        #pragma unroll
        for (int i = 0; i < 16; i++) {
            uint2 u = make_uint2(f2tf32(acc[i][0]), f2tf32(acc[i][1]));
            *(uint2*)(Zu + eloc * 1028 + i * 64 + lane * 2) = u;
        }
    }
    __syncthreads();

    // ---- phase 2: warp w computes Z(16 x K[w*128..]) @ Wb slice -> partial ----
    {
        const int kbase = warp * 128;
        float acc[8][4];
        #pragma unroll
        for (int ni = 0; ni < 8; ni++)
            #pragma unroll
            for (int q = 0; q < 4; q++) acc[ni][q] = 0.f;

        #pragma unroll 4
        for (int kk = 0; kk < 16; kk++) {
            const int k8 = kbase + kk * 8;
            uint32_t a0 = Zu[(grp    ) * 1028 + k8 + thr4    ];
            uint32_t a1 = Zu[(grp + 8) * 1028 + k8 + thr4    ];
            uint32_t a2 = Zu[(grp    ) * 1028 + k8 + thr4 + 4];
            uint32_t a3 = Zu[(grp + 8) * 1028 + k8 + thr4 + 4];
            #pragma unroll
            for (int ni = 0; ni < 8; ni++) {
                uint32_t b0 = f2tf32(__ldg(&Wb[(size_t)(k8 + thr4    ) * 64 + ni * 8 + grp]));
                uint32_t b1 = f2tf32(__ldg(&Wb[(size_t)(k8 + thr4 + 4) * 64 + ni * 8 + grp]));
                mma_tf32(acc[ni][0], acc[ni][1], acc[ni][2], acc[ni][3],
                         a0, a1, a2, a3, b0, b1);
            }
        }

        float* myP = Ps + warp * (16 * 68);
        #pragma unroll
        for (int ni = 0; ni < 8; ni++) {
            int c = ni * 8 + thr4 * 2;
            *(float2*)(myP + (grp    ) * 68 + c) = make_float2(acc[ni][0], acc[ni][1]);
            *(float2*)(myP + (grp + 8) * 68 + c) = make_float2(acc[ni][2], acc[ni][3]);
        }
    }
    __syncthreads();

    // ---- reduction: 1024 outputs, thread t -> row t/16, cols (t%16)*4 ----
    {
        const int row = tid >> 4;
        const int c0  = (tid & 15) * 4;
        float4 sum = make_float4(0.f, 0.f, 0.f, 0.f);
        #pragma unroll
        for (int w = 0; w < 8; w++) {
            float4 p = *(const float4*)(Ps + w * (16 * 68) + row * 68 + c0);
            sum.x += p.x; sum.y += p.y; sum.z += p.z; sum.w += p.w;
        }
        const float sc = *s_cbf;
        sum.x *= sc; sum.y *= sc; sum.z *= sc; sum.w *= sc;
        *(float4*)(X + (size_t)(e0 + row) * 64 + c0) = sum;
    }
}

// ---------------------------------------------------------------------------
// Output (tensor core, tf32):
// out[e,c] = (silu(x[e]@W_st[:,c]) + silu(x[idx_swap[e]]@W_ts[:,c])) / sqrt(2)
// BM=64 edges, BN=128 cols, K=64 in smem. 8 warps (4m x 2n).
// ---------------------------------------------------------------------------
__global__ void __launch_bounds__(256, 2)
k_out_tc(const float* __restrict__ Wst, const float* __restrict__ Wts,
         const int* __restrict__ idx_swap, const float* __restrict__ X,
         float* __restrict__ out, int M)
{
    extern __shared__ __align__(16) uint32_t sm_u[];
    uint32_t* X1s = sm_u;                 // [64][68]
    uint32_t* X2s = X1s + 64 * 68;        // [64][68]
    uint32_t* W1s = X2s + 64 * 68;        // [64][136]
    uint32_t* W2s = W1s + 64 * 136;       // [64][136]

    const int tid  = threadIdx.x;
    const int warp = tid >> 5;
    const int lane = tid & 31;
    const int grp  = lane >> 2;
    const int thr4 = lane & 3;
    const int warp_m = warp & 3;
    const int warp_n = warp >> 2;
    const int e0 = blockIdx.y * 64;
    const int col0 = blockIdx.x * 128;

    #pragma unroll
    for (int p = 0; p < 4; p++) {
        int idx = p * 256 + tid;
        int r = idx >> 4, q = (idx & 15) * 4;
        float4 v = *(const float4*)(X + (size_t)(e0 + r) * 64 + q);
        *(uint4*)(X1s + r * 68 + q) =
            make_uint4(f2tf32(v.x), f2tf32(v.y), f2tf32(v.z), f2tf32(v.w));
        int ge = __ldg(&idx_swap[e0 + r]);
        float4 g = *(const float4*)(X + (size_t)ge * 64 + q);
        *(uint4*)(X2s + r * 68 + q) =
            make_uint4(f2tf32(g.x), f2tf32(g.y), f2tf32(g.z), f2tf32(g.w));
    }
    #pragma unroll
    for (int p = 0; p < 8; p++) {
        int idx = p * 256 + tid;
        int r = idx >> 5, c4 = (idx & 31) * 4;
        float4 v1 = *(const float4*)(Wst + (size_t)r * 512 + col0 + c4);
        *(uint4*)(W1s + r * 136 + c4) =
            make_uint4(f2tf32(v1.x), f2tf32(v1.y), f2tf32(v1.z), f2tf32(v1.w));
        float4 v2 = *(const float4*)(Wts + (size_t)r * 512 + col0 + c4);
        *(uint4*)(W2s + r * 136 + c4) =
            make_uint4(f2tf32(v2.x), f2tf32(v2.y), f2tf32(v2.z), f2tf32(v2.w));
    }
    __syncthreads();

    float accA[8][4], accB[8][4];
    #pragma unroll
    for (int ni = 0; ni < 8; ni++)
        #pragma unroll
        for (int q = 0; q < 4; q++) { accA[ni][q] = 0.f; accB[ni][q] = 0.f; }

    const int rA = warp_m * 16 + grp;
    #pragma unroll
    for (int k8 = 0; k8 < 64; k8 += 8) {
        uint32_t a1[4], a2[4];
        a1[0] = X1s[(rA    ) * 68 + k8 + thr4    ];
        a1[1] = X1s[(rA + 8) * 68 + k8 + thr4    ];
        a1[2] = X1s[(rA    ) * 68 + k8 + thr4 + 4];
        a1[3] = X1s[(rA + 8) * 68 + k8 + thr4 + 4];
        a2[0] = X2s[(rA    ) * 68 + k8 + thr4    ];
        a2[1] = X2s[(rA + 8) * 68 + k8 + thr4    ];
        a2[2] = X2s[(rA    ) * 68 + k8 + thr4 + 4];
        a2[3] = X2s[(rA + 8) * 68 + k8 + thr4 + 4];
        #pragma unroll
        for (int ni = 0; ni < 8; ni++) {
            int c = warp_n * 64 + ni * 8 + grp;
            uint32_t b10 = W1s[(k8 + thr4    ) * 136 + c];
            uint32_t b11 = W1s[(k8 + thr4 + 4) * 136 + c];
            uint32_t b20 = W2s[(k8 + thr4    ) * 136 + c];
            uint32_t b21 = W2s[(k8 + thr4 + 4) * 136 + c];
            mma_tf32(accA[ni][0], accA[ni][1], accA[ni][2], accA[ni][3],
                     a1[0], a1[1], a1[2], a1[3], b10, b11);
            mma_tf32(accB[ni][0], accB[ni][1], accB[ni][2], accB[ni][3],
                     a2[0], a2[1], a2[2], a2[3], b20, b21);
        }
    }

    const float inv_sqrt2 = 0.70710678118654752f;
    int r_lo = e0 + warp_m * 16 + grp;
    int r_hi = r_lo + 8;
    #pragma unroll
    for (int ni = 0; ni < 8; ni++) {
        int c = col0 + warp_n * 64 + ni * 8 + thr4 * 2;
        float2 o_lo, o_hi;
        o_lo.x = (silu_f(accA[ni][0]) + silu_f(accB[ni][0])) * inv_sqrt2;
        o_lo.y = (silu_f(accA[ni][1]) + silu_f(accB[ni][1])) * inv_sqrt2;
        o_hi.x = (silu_f(accA[ni][2]) + silu_f(accB[ni][2])) * inv_sqrt2;
        o_hi.y = (silu_f(accA[ni][3]) + silu_f(accB[ni][3])) * inv_sqrt2;
        *(float2*)(out + (size_t)r_lo * 512 + c) = o_lo;
        *(float2*)(out + (size_t)r_hi * 512 + c) = o_hi;
    }
}

// ---------------------------------------------------------------------------
extern "C" void kernel_launch(void* const* d_in, const int* in_sizes, int n_in,
                              void* d_out, int out_size)
{
    const float* m_st     = (const float*)d_in[0];
    const float* rbf      = (const float*)d_in[1];
    const float* cbf      = (const float*)d_in[2];
    const int*   idx_swap = (const int*)  d_in[3];
    const int*   id3_kt   = (const int*)  d_in[4];
    const int*   id3_st   = (const int*)  d_in[5];
    /* d_in[6] = id3_ragged_idx (unused) */
    const float* W_mkt    = (const float*)d_in[7];
    const float* W_rbf    = (const float*)d_in[8];
    const float* W_down   = (const float*)d_in[9];
    const float* W_bil    = (const float*)d_in[10];
    const float* W_st     = (const float*)d_in[11];
    const float* W_ts     = (const float*)d_in[12];
    const float* s_rbf    = (const float*)d_in[13];
    const float* s_cbf    = (const float*)d_in[14];
    float* out = (float*)d_out;

    const int M  = in_sizes[0] / EMB_EDGE;   // 65536
    const int Tn = in_sizes[2] / EMB_CBF;    // 262144

    float *p_h1, *p_mkt, *p_x;
    cudaGetSymbolAddress((void**)&p_h1,  g_h1);
    cudaGetSymbolAddress((void**)&p_mkt, g_mkt);
    cudaGetSymbolAddress((void**)&p_x,   g_x);

    // 1. h1 = silu(m_st @ W_mkt) * (rbf @ W_rbf) * s_rbf   [tf32, cp.async 2-stage]
    cudaFuncSetAttribute(k_gemm1_tc, cudaFuncAttributeMaxDynamicSharedMemorySize, G1_SMEM);
    k_gemm1_tc<<<dim3(4, M / 128), 256, G1_SMEM>>>(m_st, W_mkt, rbf, W_rbf, s_rbf, p_h1, M);
    // 2. m_kt = silu(h1 @ W_down)                          [tf32]
    k_gemm2_tc<<<dim3(1, M / 128), 256>>>(p_h1, W_down, p_mkt, M);
    // 3. segment pointers from sorted id3_st
    k_segptr<<<(M + 256) / 256, 256>>>(id3_st, Tn, M);
    // 4+5 fused: x = (segment_sum(cbf outer m_t) @ W_bil) * s_cbf   [tf32, K-split]
    cudaFuncSetAttribute(k_bilx, cudaFuncAttributeMaxDynamicSharedMemorySize, BILX_SMEM);
    k_bilx<<<M / 16, 256, BILX_SMEM>>>(cbf, id3_kt, W_bil, s_cbf, p_x);
    // 6. out = (silu(x@W_st) + silu(x[swap]@W_ts)) / sqrt(2)   [tf32]
    {
        const int smem = (2 * 64 * 68 + 2 * 64 * 136) * 4;   // 104448 B
        cudaFuncSetAttribute(k_out_tc, cudaFuncAttributeMaxDynamicSharedMemorySize, smem);
        k_out_tc<<<dim3(4, M / 64), 256, smem>>>(W_st, W_ts, idx_swap, p_x, out, M);
    }
}

// round 6
// speedup vs baseline: 2.7992x; 1.2505x over previous
#include <cuda_runtime.h>
#include <math.h>
#include <stdint.h>

#define EMB_EDGE 512
#define EMB_RBF  16
#define EMB_CBF  16
#define EMB_TRI  64
#define EMB_BIL  64
#define E_MAX    65536
#define T_MAX    262144

// scratch (device globals: allocation-free rule)
__device__ float    g_h1[(size_t)E_MAX * EMB_EDGE];   // 128 MB
__device__ float    g_mkt[(size_t)E_MAX * EMB_TRI];   // 16 MB
__device__ float    g_x[(size_t)E_MAX * EMB_BIL];     // 16 MB
__device__ int      g_segptr[E_MAX + 1];
// prepacked weights (tf32 bit patterns)
__device__ uint32_t g_WmT[512 * 512];
__device__ uint32_t g_WdT[512 * 64];
__device__ uint32_t g_WstT[64 * 512];
__device__ uint32_t g_WtsT[64 * 512];
__device__ uint2    g_WbP[8 * 16 * 8 * 32];   // [kwarp][kk][ni][lane]

__device__ __forceinline__ float silu_f(float v) {
    return v / (1.0f + __expf(-v));
}

__device__ __forceinline__ uint32_t f2tf32(float f) {
    uint32_t u;
    asm("cvt.rna.tf32.f32 %0, %1;" : "=r"(u) : "f"(f));
    return u;
}

__device__ __forceinline__ void mma_tf32(float& d0, float& d1, float& d2, float& d3,
                                         uint32_t a0, uint32_t a1, uint32_t a2, uint32_t a3,
                                         uint32_t b0, uint32_t b1)
{
    asm volatile(
        "mma.sync.aligned.m16n8k8.row.col.f32.tf32.tf32.f32 "
        "{%0,%1,%2,%3}, {%4,%5,%6,%7}, {%8,%9}, {%0,%1,%2,%3};\n"
        : "+f"(d0), "+f"(d1), "+f"(d2), "+f"(d3)
        : "r"(a0), "r"(a1), "r"(a2), "r"(a3), "r"(b0), "r"(b1));
}

#define CP_ASYNC16(dst_u32, src_ptr) \
    asm volatile("cp.async.ca.shared.global [%0], [%1], 16;" :: "r"(dst_u32), "l"(src_ptr))
#define CP_COMMIT() asm volatile("cp.async.commit_group;")
#define CP_WAIT1()  asm volatile("cp.async.wait_group 1;")
#define CP_WAIT0()  asm volatile("cp.async.wait_group 0;")

// ---------------------------------------------------------------------------
// Prepack: convert weights to tf32 bits; W_bil into MMA B-fragment layout.
// grid = 480 blocks x 256 thr
// ---------------------------------------------------------------------------
__global__ void k_prepack(const float* __restrict__ Wm, const float* __restrict__ Wd,
                          const float* __restrict__ Ws, const float* __restrict__ Wt,
                          const float* __restrict__ Wb)
{
    const int b = blockIdx.x, tid = threadIdx.x;
    if (b < 256) {               // W_mkt: 262144 floats, 4/thread
        int i = (b * 256 + tid) * 4;
        float4 v = *(const float4*)(Wm + i);
        *(uint4*)(g_WmT + i) = make_uint4(f2tf32(v.x), f2tf32(v.y), f2tf32(v.z), f2tf32(v.w));
    } else if (b < 288) {        // W_down: 32768 floats
        int i = ((b - 256) * 256 + tid) * 4;
        float4 v = *(const float4*)(Wd + i);
        *(uint4*)(g_WdT + i) = make_uint4(f2tf32(v.x), f2tf32(v.y), f2tf32(v.z), f2tf32(v.w));
    } else if (b < 320) {        // W_st
        int i = ((b - 288) * 256 + tid) * 4;
        float4 v = *(const float4*)(Ws + i);
        *(uint4*)(g_WstT + i) = make_uint4(f2tf32(v.x), f2tf32(v.y), f2tf32(v.z), f2tf32(v.w));
    } else if (b < 352) {        // W_ts
        int i = ((b - 320) * 256 + tid) * 4;
        float4 v = *(const float4*)(Wt + i);
        *(uint4*)(g_WtsT + i) = make_uint4(f2tf32(v.x), f2tf32(v.y), f2tf32(v.z), f2tf32(v.w));
    } else {                     // W_bil fragments: 32768 uint2
        int e = (b - 352) * 256 + tid;
        int lane = e & 31, ni = (e >> 5) & 7, kk = (e >> 8) & 15, w = e >> 12;
        int k = w * 128 + kk * 8 + (lane & 3);
        int n = ni * 8 + (lane >> 2);
        g_WbP[e] = make_uint2(f2tf32(Wb[(size_t)k * 64 + n]),
                              f2tf32(Wb[(size_t)(k + 4) * 64 + n]));
    }
}

// ---------------------------------------------------------------------------
// Kernel 1 (tf32, 2-stage cp.async): h1 = silu(m_st@W_mkt) * (rbf@W_rbf) * s
// B comes pre-converted (g_WmT) -> no cvt on B fragments.
// ---------------------------------------------------------------------------
#define A_PAD 36
#define B_PAD 136
#define G1_AS (128 * A_PAD)
#define G1_BS (32 * B_PAD)
#define G1_STAGE (G1_AS + G1_BS)
#define G1_SMEM (2 * G1_STAGE * 4)

__device__ __forceinline__ void g1_load_stage(float* As, uint32_t* Bs,
                                              const float* __restrict__ A,
                                              const uint32_t* __restrict__ B,
                                              int row0, int col0, int k0, int tid)
{
    const int a_row = tid >> 3, a_kq = (tid & 7) * 4;
    #pragma unroll
    for (int p = 0; p < 4; p++) {
        int row = a_row + p * 32;
        uint32_t d = (uint32_t)__cvta_generic_to_shared(As + row * A_PAD + a_kq);
        CP_ASYNC16(d, A + (size_t)(row0 + row) * 512 + k0 + a_kq);
    }
    const int b_r = tid >> 5, b_c = (tid & 31) * 4;
    #pragma unroll
    for (int p = 0; p < 4; p++) {
        int r = b_r + p * 8;
        uint32_t d = (uint32_t)__cvta_generic_to_shared(Bs + r * B_PAD + b_c);
        CP_ASYNC16(d, B + (size_t)(k0 + r) * 512 + col0 + b_c);
    }
}

__global__ void __launch_bounds__(256, 2)
k_gemm1_tc(const float* __restrict__ A, const uint32_t* __restrict__ B,
           const float* __restrict__ rbf, const float* __restrict__ Wr,
           const float* __restrict__ s_rbf, float* __restrict__ C, int M)
{
    extern __shared__ __align__(16) float sm_g1[];

    const int tid  = threadIdx.x;
    const int warp = tid >> 5;
    const int lane = tid & 31;
    const int grp  = lane >> 2;
    const int thr4 = lane & 3;
    const int warp_m = warp & 3;
    const int warp_n = warp >> 2;
    const int row0 = blockIdx.y * 128;
    const int col0 = blockIdx.x * 128;

    float acc[2][8][4];
    #pragma unroll
    for (int mi = 0; mi < 2; mi++)
        #pragma unroll
        for (int ni = 0; ni < 8; ni++)
            #pragma unroll
            for (int q = 0; q < 4; q++) acc[mi][ni][q] = 0.f;

    g1_load_stage(sm_g1, (uint32_t*)(sm_g1 + G1_AS), A, B, row0, col0, 0, tid);
    CP_COMMIT();

    #pragma unroll 1
    for (int it = 0; it < 16; it++) {
        const int buf = it & 1;
        float* stage = sm_g1 + buf * G1_STAGE;
        if (it + 1 < 16) {
            float* nstage = sm_g1 + (buf ^ 1) * G1_STAGE;
            g1_load_stage(nstage, (uint32_t*)(nstage + G1_AS), A, B,
                          row0, col0, (it + 1) * 32, tid);
            CP_COMMIT();
            CP_WAIT1();
        } else {
            CP_WAIT0();
        }
        __syncthreads();

        const float* Asf = stage;
        const uint32_t* Bsu = (const uint32_t*)(stage + G1_AS);
        #pragma unroll
        for (int kk = 0; kk < 4; kk++) {
            const int k8 = kk * 8;
            uint32_t a[2][4], b[8][2];
            #pragma unroll
            for (int mi = 0; mi < 2; mi++) {
                int r = warp_m * 32 + mi * 16 + grp;
                a[mi][0] = f2tf32(Asf[(r    ) * A_PAD + k8 + thr4    ]);
                a[mi][1] = f2tf32(Asf[(r + 8) * A_PAD + k8 + thr4    ]);
                a[mi][2] = f2tf32(Asf[(r    ) * A_PAD + k8 + thr4 + 4]);
                a[mi][3] = f2tf32(Asf[(r + 8) * A_PAD + k8 + thr4 + 4]);
            }
            #pragma unroll
            for (int ni = 0; ni < 8; ni++) {
                int c = warp_n * 64 + ni * 8 + grp;
                b[ni][0] = Bsu[(k8 + thr4    ) * B_PAD + c];
                b[ni][1] = Bsu[(k8 + thr4 + 4) * B_PAD + c];
            }
            #pragma unroll
            for (int mi = 0; mi < 2; mi++)
                #pragma unroll
                for (int ni = 0; ni < 8; ni++)
                    mma_tf32(acc[mi][ni][0], acc[mi][ni][1], acc[mi][ni][2], acc[mi][ni][3],
                             a[mi][0], a[mi][1], a[mi][2], a[mi][3],
                             b[ni][0], b[ni][1]);
        }
        __syncthreads();
    }

    // epilogue: mod = rbf(128x16) @ Wr(16x128) in fp32
    float* rbf_s = sm_g1;                 // [128][17]
    float* Wr_s  = rbf_s + 128 * 17;      // [16][132]
    {
        int r = tid >> 1, q0 = (tid & 1) * 8;
        float4 v0 = *(const float4*)(rbf + (size_t)(row0 + r) * 16 + q0);
        float4 v1 = *(const float4*)(rbf + (size_t)(row0 + r) * 16 + q0 + 4);
        rbf_s[r * 17 + q0 + 0] = v0.x; rbf_s[r * 17 + q0 + 1] = v0.y;
        rbf_s[r * 17 + q0 + 2] = v0.z; rbf_s[r * 17 + q0 + 3] = v0.w;
        rbf_s[r * 17 + q0 + 4] = v1.x; rbf_s[r * 17 + q0 + 5] = v1.y;
        rbf_s[r * 17 + q0 + 6] = v1.z; rbf_s[r * 17 + q0 + 7] = v1.w;
        int q = tid >> 4, c = (tid & 15) * 8;
        float4 w0 = *(const float4*)(Wr + (size_t)q * 512 + col0 + c);
        float4 w1 = *(const float4*)(Wr + (size_t)q * 512 + col0 + c + 4);
        *(float4*)(Wr_s + q * 132 + c)     = w0;
        *(float4*)(Wr_s + q * 132 + c + 4) = w1;
    }
    __syncthreads();

    const float s = *s_rbf;
    #pragma unroll
    for (int mi = 0; mi < 2; mi++) {
        int r_lo = warp_m * 32 + mi * 16 + grp;
        int r_hi = r_lo + 8;
        float rlo[16], rhi[16];
        #pragma unroll
        for (int q = 0; q < 16; q++) {
            rlo[q] = rbf_s[r_lo * 17 + q];
            rhi[q] = rbf_s[r_hi * 17 + q];
        }
        #pragma unroll
        for (int ni = 0; ni < 8; ni++) {
            int c_s = warp_n * 64 + ni * 8 + thr4 * 2;
            float m00 = 0.f, m01 = 0.f, m10 = 0.f, m11 = 0.f;
            #pragma unroll
            for (int q = 0; q < 16; q++) {
                float w0 = Wr_s[q * 132 + c_s];
                float w1 = Wr_s[q * 132 + c_s + 1];
                m00 = fmaf(rlo[q], w0, m00); m01 = fmaf(rlo[q], w1, m01);
                m10 = fmaf(rhi[q], w0, m10); m11 = fmaf(rhi[q], w1, m11);
            }
            float2 o_lo, o_hi;
            o_lo.x = silu_f(acc[mi][ni][0]) * m00 * s;
            o_lo.y = silu_f(acc[mi][ni][1]) * m01 * s;
            o_hi.x = silu_f(acc[mi][ni][2]) * m10 * s;
            o_hi.y = silu_f(acc[mi][ni][3]) * m11 * s;
            *(float2*)(C + (size_t)(row0 + r_lo) * 512 + col0 + c_s) = o_lo;
            *(float2*)(C + (size_t)(row0 + r_hi) * 512 + col0 + c_s) = o_hi;
        }
    }
}

// ---------------------------------------------------------------------------
// Kernel 2 (tf32): m_kt = silu(h1 @ W_down). B pre-converted.
// ---------------------------------------------------------------------------
__global__ void k_gemm2_tc(const float* __restrict__ A, const uint32_t* __restrict__ B,
                           float* __restrict__ C, int M)
{
    __shared__ __align__(16) uint32_t As[128 * A_PAD];
    __shared__ __align__(16) uint32_t Bs[32 * 72];

    const int tid  = threadIdx.x;
    const int warp = tid >> 5;
    const int lane = tid & 31;
    const int grp  = lane >> 2;
    const int thr4 = lane & 3;
    const int row0 = blockIdx.y * 128;

    float acc[8][4];
    #pragma unroll
    for (int ni = 0; ni < 8; ni++)
        #pragma unroll
        for (int q = 0; q < 4; q++) acc[ni][q] = 0.f;

    const int a_row = tid >> 3;
    const int a_kq  = (tid & 7) * 4;

    for (int k0 = 0; k0 < 512; k0 += 32) {
        #pragma unroll
        for (int p = 0; p < 4; p++) {
            int row = a_row + p * 32;
            float4 v = *(const float4*)(A + (size_t)(row0 + row) * 512 + k0 + a_kq);
            uint4 u = make_uint4(f2tf32(v.x), f2tf32(v.y), f2tf32(v.z), f2tf32(v.w));
            *(uint4*)(As + row * A_PAD + a_kq) = u;
        }
        #pragma unroll
        for (int p = 0; p < 2; p++) {
            int idx = p * 256 + tid;
            int r = idx >> 4, c = (idx & 15) * 4;
            *(uint4*)(Bs + r * 72 + c) = *(const uint4*)(B + (size_t)(k0 + r) * 64 + c);
        }
        __syncthreads();

        #pragma unroll
        for (int kk = 0; kk < 4; kk++) {
            const int k8 = kk * 8;
            int r = warp * 16 + grp;
            uint32_t a0 = As[(r    ) * A_PAD + k8 + thr4    ];
            uint32_t a1 = As[(r + 8) * A_PAD + k8 + thr4    ];
            uint32_t a2 = As[(r    ) * A_PAD + k8 + thr4 + 4];
            uint32_t a3 = As[(r + 8) * A_PAD + k8 + thr4 + 4];
            #pragma unroll
            for (int ni = 0; ni < 8; ni++) {
                uint32_t b0 = Bs[(k8 + thr4    ) * 72 + ni * 8 + grp];
                uint32_t b1 = Bs[(k8 + thr4 + 4) * 72 + ni * 8 + grp];
                mma_tf32(acc[ni][0], acc[ni][1], acc[ni][2], acc[ni][3],
                         a0, a1, a2, a3, b0, b1);
            }
        }
        __syncthreads();
    }

    int r_lo = row0 + warp * 16 + grp;
    int r_hi = r_lo + 8;
    #pragma unroll
    for (int ni = 0; ni < 8; ni++) {
        int c = ni * 8 + thr4 * 2;
        float2 o_lo = make_float2(silu_f(acc[ni][0]), silu_f(acc[ni][1]));
        float2 o_hi = make_float2(silu_f(acc[ni][2]), silu_f(acc[ni][3]));
        *(float2*)(C + (size_t)r_lo * 64 + c) = o_lo;
        *(float2*)(C + (size_t)r_hi * 64 + c) = o_hi;
    }
}

// ---------------------------------------------------------------------------
// segment pointers
// ---------------------------------------------------------------------------
__global__ void k_segptr(const int* __restrict__ st, int Tn, int M)
{
    int e = blockIdx.x * blockDim.x + threadIdx.x;
    if (e > M) return;
    if (e == M) { g_segptr[M] = Tn; return; }
    int lo = 0, hi = Tn;
    while (lo < hi) {
        int mid = (lo + hi) >> 1;
        if (st[mid] < e) lo = mid + 1; else hi = mid;
    }
    g_segptr[e] = lo;
}

// ---------------------------------------------------------------------------
// Fused bilinear: x = (segment_sum(cbf outer m_kt[kt]) @ W_bil) * s_cbf
// Phase 1: warp w -> edges w*2, w*2+1; uniform cbf float4 loads (no shfl),
//          depth-1 pipelined id3_kt -> m_kt chain.
// Phase 2: K-split, B-fragments from prepacked g_WbP (coalesced LDG.64).
// ---------------------------------------------------------------------------
#define BILX_Z   (16 * 1028)
#define BILX_P   (8 * 16 * 68)
#define BILX_SMEM ((BILX_Z + BILX_P) * 4)

__global__ void __launch_bounds__(256, 2)
k_bilx(const float* __restrict__ cbf, const int* __restrict__ id3_kt,
       const float* __restrict__ s_cbf, float* __restrict__ X)
{
    extern __shared__ __align__(16) uint32_t sm_bx[];
    uint32_t* Zu = sm_bx;                    // [16][1028] tf32
    float*    Ps = (float*)(sm_bx + BILX_Z); // [8][16][68] fp32 partials

    const int tid  = threadIdx.x;
    const int warp = tid >> 5;
    const int lane = tid & 31;
    const int grp  = lane >> 2;
    const int thr4 = lane & 3;
    const int e0 = blockIdx.x * 16;

    // ---- phase 1 ----
    #pragma unroll
    for (int sub = 0; sub < 2; sub++) {
        const int eloc = warp * 2 + sub;
        const int e = e0 + eloc;
        const int t0 = g_segptr[e], t1 = g_segptr[e + 1];
        float acc[16][2];
        #pragma unroll
        for (int i = 0; i < 16; i++) { acc[i][0] = 0.f; acc[i][1] = 0.f; }

        float2 m2 = make_float2(0.f, 0.f);
        float4 cb0, cb1, cb2, cb3;
        if (t0 < t1) {
            int kt = __ldg(&id3_kt[t0]);
            m2  = *(const float2*)(g_mkt + (size_t)kt * 64 + lane * 2);
            cb0 = __ldg((const float4*)(cbf + (size_t)t0 * 16));
            cb1 = __ldg((const float4*)(cbf + (size_t)t0 * 16 + 4));
            cb2 = __ldg((const float4*)(cbf + (size_t)t0 * 16 + 8));
            cb3 = __ldg((const float4*)(cbf + (size_t)t0 * 16 + 12));
        }
        for (int t = t0; t < t1; t++) {
            float2 m2n = make_float2(0.f, 0.f);
            float4 nb0, nb1, nb2, nb3;
            if (t + 1 < t1) {
                int ktn = __ldg(&id3_kt[t + 1]);
                m2n = *(const float2*)(g_mkt + (size_t)ktn * 64 + lane * 2);
                nb0 = __ldg((const float4*)(cbf + (size_t)(t + 1) * 16));
                nb1 = __ldg((const float4*)(cbf + (size_t)(t + 1) * 16 + 4));
                nb2 = __ldg((const float4*)(cbf + (size_t)(t + 1) * 16 + 8));
                nb3 = __ldg((const float4*)(cbf + (size_t)(t + 1) * 16 + 12));
            }
            acc[ 0][0] = fmaf(cb0.x, m2.x, acc[ 0][0]); acc[ 0][1] = fmaf(cb0.x, m2.y, acc[ 0][1]);
            acc[ 1][0] = fmaf(cb0.y, m2.x, acc[ 1][0]); acc[ 1][1] = fmaf(cb0.y, m2.y, acc[ 1][1]);
            acc[ 2][0] = fmaf(cb0.z, m2.x, acc[ 2][0]); acc[ 2][1] = fmaf(cb0.z, m2.y, acc[ 2][1]);
            acc[ 3][0] = fmaf(cb0.w, m2.x, acc[ 3][0]); acc[ 3][1] = fmaf(cb0.w, m2.y, acc[ 3][1]);
            acc[ 4][0] = fmaf(cb1.x, m2.x, acc[ 4][0]); acc[ 4][1] = fmaf(cb1.x, m2.y, acc[ 4][1]);
            acc[ 5][0] = fmaf(cb1.y, m2.x, acc[ 5][0]); acc[ 5][1] = fmaf(cb1.y, m2.y, acc[ 5][1]);
            acc[ 6][0] = fmaf(cb1.z, m2.x, acc[ 6][0]); acc[ 6][1] = fmaf(cb1.z, m2.y, acc[ 6][1]);
            acc[ 7][0] = fmaf(cb1.w, m2.x, acc[ 7][0]); acc[ 7][1] = fmaf(cb1.w, m2.y, acc[ 7][1]);
            acc[ 8][0] = fmaf(cb2.x, m2.x, acc[ 8][0]); acc[ 8][1] = fmaf(cb2.x, m2.y, acc[ 8][1]);
            acc[ 9][0] = fmaf(cb2.y, m2.x, acc[ 9][0]); acc[ 9][1] = fmaf(cb2.y, m2.y, acc[ 9][1]);
            acc[10][0] = fmaf(cb2.z, m2.x, acc[10][0]); acc[10][1] = fmaf(cb2.z, m2.y, acc[10][1]);
            acc[11][0] = fmaf(cb2.w, m2.x, acc[11][0]); acc[11][1] = fmaf(cb2.w, m2.y, acc[11][1]);
            acc[12][0] = fmaf(cb3.x, m2.x, acc[12][0]); acc[12][1] = fmaf(cb3.x, m2.y, acc[12][1]);
            acc[13][0] = fmaf(cb3.y, m2.x, acc[13][0]); acc[13][1] = fmaf(cb3.y, m2.y, acc[13][1]);
            acc[14][0] = fmaf(cb3.z, m2.x, acc[14][0]); acc[14][1] = fmaf(cb3.z, m2.y, acc[14][1]);
            acc[15][0] = fmaf(cb3.w, m2.x, acc[15][0]); acc[15][1] = fmaf(cb3.w, m2.y, acc[15][1]);
            m2 = m2n; cb0 = nb0; cb1 = nb1; cb2 = nb2; cb3 = nb3;
        }
        #pragma unroll
        for (int i = 0; i < 16; i++) {
            uint2 u = make_uint2(f2tf32(acc[i][0]), f2tf32(acc[i][1]));
            *(uint2*)(Zu + eloc * 1028 + i * 64 + lane * 2) = u;
        }
    }
    __syncthreads();

    // ---- phase 2: warp w -> K slice [w*128, (w+1)*128), prepacked B ----
    {
        const int kbase = warp * 128;
        const uint2* wp = g_WbP + (size_t)warp * (16 * 8 * 32) + lane;
        float acc[8][4];
        #pragma unroll
        for (int ni = 0; ni < 8; ni++)
            #pragma unroll
            for (int q = 0; q < 4; q++) acc[ni][q] = 0.f;

        #pragma unroll 4
        for (int kk = 0; kk < 16; kk++) {
            const int k8 = kbase + kk * 8;
            uint32_t a0 = Zu[(grp    ) * 1028 + k8 + thr4    ];
            uint32_t a1 = Zu[(grp + 8) * 1028 + k8 + thr4    ];
            uint32_t a2 = Zu[(grp    ) * 1028 + k8 + thr4 + 4];
            uint32_t a3 = Zu[(grp + 8) * 1028 + k8 + thr4 + 4];
            #pragma unroll
            for (int ni = 0; ni < 8; ni++) {
                uint2 bv = __ldg(wp + (kk * 8 + ni) * 32);
                mma_tf32(acc[ni][0], acc[ni][1], acc[ni][2], acc[ni][3],
                         a0, a1, a2, a3, bv.x, bv.y);
            }
        }

        float* myP = Ps + warp * (16 * 68);
        #pragma unroll
        for (int ni = 0; ni < 8; ni++) {
            int c = ni * 8 + thr4 * 2;
            *(float2*)(myP + (grp    ) * 68 + c) = make_float2(acc[ni][0], acc[ni][1]);
            *(float2*)(myP + (grp + 8) * 68 + c) = make_float2(acc[ni][2], acc[ni][3]);
        }
    }
    __syncthreads();

    // ---- reduction ----
    {
        const int row = tid >> 4;
        const int c0  = (tid & 15) * 4;
        float4 sum = make_float4(0.f, 0.f, 0.f, 0.f);
        #pragma unroll
        for (int w = 0; w < 8; w++) {
            float4 p = *(const float4*)(Ps + w * (16 * 68) + row * 68 + c0);
            sum.x += p.x; sum.y += p.y; sum.z += p.z; sum.w += p.w;
        }
        const float sc = *s_cbf;
        sum.x *= sc; sum.y *= sc; sum.z *= sc; sum.w *= sc;
        *(float4*)(X + (size_t)(e0 + row) * 64 + c0) = sum;
    }
}

// ---------------------------------------------------------------------------
// Output (tf32): out = (silu(x@W_st) + silu(x[swap]@W_ts)) / sqrt(2)
// W pre-converted -> no cvt on W tiles.
// ---------------------------------------------------------------------------
__global__ void __launch_bounds__(256, 2)
k_out_tc(const uint32_t* __restrict__ Wst, const uint32_t* __restrict__ Wts,
         const int* __restrict__ idx_swap, const float* __restrict__ X,
         float* __restrict__ out, int M)
{
    extern __shared__ __align__(16) uint32_t sm_u[];
    uint32_t* X1s = sm_u;                 // [64][68]
    uint32_t* X2s = X1s + 64 * 68;        // [64][68]
    uint32_t* W1s = X2s + 64 * 68;        // [64][136]
    uint32_t* W2s = W1s + 64 * 136;       // [64][136]

    const int tid  = threadIdx.x;
    const int warp = tid >> 5;
    const int lane = tid & 31;
    const int grp  = lane >> 2;
    const int thr4 = lane & 3;
    const int warp_m = warp & 3;
    const int warp_n = warp >> 2;
    const int e0 = blockIdx.y * 64;
    const int col0 = blockIdx.x * 128;

    #pragma unroll
    for (int p = 0; p < 4; p++) {
        int idx = p * 256 + tid;
        int r = idx >> 4, q = (idx & 15) * 4;
        float4 v = *(const float4*)(X + (size_t)(e0 + r) * 64 + q);
        *(uint4*)(X1s + r * 68 + q) =
            make_uint4(f2tf32(v.x), f2tf32(v.y), f2tf32(v.z), f2tf32(v.w));
        int ge = __ldg(&idx_swap[e0 + r]);
        float4 g = *(const float4*)(X + (size_t)ge * 64 + q);
        *(uint4*)(X2s + r * 68 + q) =
            make_uint4(f2tf32(g.x), f2tf32(g.y), f2tf32(g.z), f2tf32(g.w));
    }
    #pragma unroll
    for (int p = 0; p < 8; p++) {
        int idx = p * 256 + tid;
        int r = idx >> 5, c4 = (idx & 31) * 4;
        *(uint4*)(W1s + r * 136 + c4) = *(const uint4*)(Wst + (size_t)r * 512 + col0 + c4);
        *(uint4*)(W2s + r * 136 + c4) = *(const uint4*)(Wts + (size_t)r * 512 + col0 + c4);
    }
    __syncthreads();

    float accA[8][4], accB[8][4];
    #pragma unroll
    for (int ni = 0; ni < 8; ni++)
        #pragma unroll
        for (int q = 0; q < 4; q++) { accA[ni][q] = 0.f; accB[ni][q] = 0.f; }

    const int rA = warp_m * 16 + grp;
    #pragma unroll
    for (int k8 = 0; k8 < 64; k8 += 8) {
        uint32_t a1[4], a2[4];
        a1[0] = X1s[(rA    ) * 68 + k8 + thr4    ];
        a1[1] = X1s[(rA + 8) * 68 + k8 + thr4    ];
        a1[2] = X1s[(rA    ) * 68 + k8 + thr4 + 4];
        a1[3] = X1s[(rA + 8) * 68 + k8 + thr4 + 4];
        a2[0] = X2s[(rA    ) * 68 + k8 + thr4    ];
        a2[1] = X2s[(rA + 8) * 68 + k8 + thr4    ];
        a2[2] = X2s[(rA    ) * 68 + k8 + thr4 + 4];
        a2[3] = X2s[(rA + 8) * 68 + k8 + thr4 + 4];
        #pragma unroll
        for (int ni = 0; ni < 8; ni++) {
            int c = warp_n * 64 + ni * 8 + grp;
            uint32_t b10 = W1s[(k8 + thr4    ) * 136 + c];
            uint32_t b11 = W1s[(k8 + thr4 + 4) * 136 + c];
            uint32_t b20 = W2s[(k8 + thr4    ) * 136 + c];
            uint32_t b21 = W2s[(k8 + thr4 + 4) * 136 + c];
            mma_tf32(accA[ni][0], accA[ni][1], accA[ni][2], accA[ni][3],
                     a1[0], a1[1], a1[2], a1[3], b10, b11);
            mma_tf32(accB[ni][0], accB[ni][1], accB[ni][2], accB[ni][3],
                     a2[0], a2[1], a2[2], a2[3], b20, b21);
        }
    }

    const float inv_sqrt2 = 0.70710678118654752f;
    int r_lo = e0 + warp_m * 16 + grp;
    int r_hi = r_lo + 8;
    #pragma unroll
    for (int ni = 0; ni < 8; ni++) {
        int c = col0 + warp_n * 64 + ni * 8 + thr4 * 2;
        float2 o_lo, o_hi;
        o_lo.x = (silu_f(accA[ni][0]) + silu_f(accB[ni][0])) * inv_sqrt2;
        o_lo.y = (silu_f(accA[ni][1]) + silu_f(accB[ni][1])) * inv_sqrt2;
        o_hi.x = (silu_f(accA[ni][2]) + silu_f(accB[ni][2])) * inv_sqrt2;
        o_hi.y = (silu_f(accA[ni][3]) + silu_f(accB[ni][3])) * inv_sqrt2;
        *(float2*)(out + (size_t)r_lo * 512 + c) = o_lo;
        *(float2*)(out + (size_t)r_hi * 512 + c) = o_hi;
    }
}

// ---------------------------------------------------------------------------
extern "C" void kernel_launch(void* const* d_in, const int* in_sizes, int n_in,
                              void* d_out, int out_size)
{
    const float* m_st     = (const float*)d_in[0];
    const float* rbf      = (const float*)d_in[1];
    const float* cbf      = (const float*)d_in[2];
    const int*   idx_swap = (const int*)  d_in[3];
    const int*   id3_kt   = (const int*)  d_in[4];
    const int*   id3_st   = (const int*)  d_in[5];
    /* d_in[6] = id3_ragged_idx (unused) */
    const float* W_mkt    = (const float*)d_in[7];
    const float* W_rbf    = (const float*)d_in[8];
    const float* W_down   = (const float*)d_in[9];
    const float* W_bil    = (const float*)d_in[10];
    const float* W_st     = (const float*)d_in[11];
    const float* W_ts     = (const float*)d_in[12];
    const float* s_rbf    = (const float*)d_in[13];
    const float* s_cbf    = (const float*)d_in[14];
    float* out = (float*)d_out;

    const int M  = in_sizes[0] / EMB_EDGE;   // 65536
    const int Tn = in_sizes[2] / EMB_CBF;    // 262144

    float *p_h1, *p_mkt, *p_x;
    uint32_t *p_WmT, *p_WdT, *p_WstT, *p_WtsT;
    cudaGetSymbolAddress((void**)&p_h1,   g_h1);
    cudaGetSymbolAddress((void**)&p_mkt,  g_mkt);
    cudaGetSymbolAddress((void**)&p_x,    g_x);
    cudaGetSymbolAddress((void**)&p_WmT,  g_WmT);
    cudaGetSymbolAddress((void**)&p_WdT,  g_WdT);
    cudaGetSymbolAddress((void**)&p_WstT, g_WstT);
    cudaGetSymbolAddress((void**)&p_WtsT, g_WtsT);

    // 0. prepack weights (tf32 bits + W_bil fragments)
    k_prepack<<<480, 256>>>(W_mkt, W_down, W_st, W_ts, W_bil);
    // 3. segment pointers (independent of prepack)
    k_segptr<<<(M + 256) / 256, 256>>>(id3_st, Tn, M);
    // 1. h1 = silu(m_st @ W_mkt) * (rbf @ W_rbf) * s_rbf
    cudaFuncSetAttribute(k_gemm1_tc, cudaFuncAttributeMaxDynamicSharedMemorySize, G1_SMEM);
    k_gemm1_tc<<<dim3(4, M / 128), 256, G1_SMEM>>>(m_st, p_WmT, rbf, W_rbf, s_rbf, p_h1, M);
    // 2. m_kt = silu(h1 @ W_down)
    k_gemm2_tc<<<dim3(1, M / 128), 256>>>(p_h1, p_WdT, p_mkt, M);
    // 4+5 fused: x = (segment_sum(cbf outer m_t) @ W_bil) * s_cbf
    cudaFuncSetAttribute(k_bilx, cudaFuncAttributeMaxDynamicSharedMemorySize, BILX_SMEM);
    k_bilx<<<M / 16, 256, BILX_SMEM>>>(cbf, id3_kt, s_cbf, p_x);
    // 6. out = (silu(x@W_st) + silu(x[swap]@W_ts)) / sqrt(2)
    {
        const int smem = (2 * 64 * 68 + 2 * 64 * 136) * 4;
        cudaFuncSetAttribute(k_out_tc, cudaFuncAttributeMaxDynamicSharedMemorySize, smem);
        k_out_tc<<<dim3(4, M / 64), 256, smem>>>(p_WstT, p_WtsT, idx_swap, p_x, out, M);
    }
}